// round 1
// baseline (speedup 1.0000x reference)
#include <cuda_runtime.h>
#include <cuda_bf16.h>
#include <math.h>

// ---------------------------------------------------------------------------
// Problem constants (shapes fixed by the dataset)
// ---------------------------------------------------------------------------
#define BATCH 8
#define NTOK 4096          // 64*64 tokens per batch
#define ROWS (BATCH*NTOK)  // 32768
#define DIMC 180
#define HEADS 6
#define HD 30
#define QKVW 540
#define MTOK 64            // token dictionary size
#define RDIM 10
#define GS 128             // group size (CAT)
#define NG 32              // groups per batch
#define WS 16
#define WINN 256           // tokens per window
#define NWIN 128           // total windows (8 * 16)
#define MLP_HID 360
#define DTD 64
#define CFF 424            // MLP_HID + DTD
#define HH 64
#define WW 64

// ---------------------------------------------------------------------------
// Scratch (static device globals; no allocation allowed)
// ---------------------------------------------------------------------------
__device__ float g_xn   [ROWS*DIMC];
__device__ float g_qkv  [ROWS*QKVW];
__device__ float g_qatd [ROWS*RDIM];
__device__ float g_kkn  [BATCH*MTOK*RDIM];
__device__ float g_vv   [BATCH*MTOK*DIMC];
__device__ float g_tdpr [BATCH*MTOK*DTD];
__device__ float g_xatd [ROWS*DIMC];
__device__ int   g_tkid [ROWS];
__device__ int   g_sidx [ROWS];
__device__ int   g_cnt  [BATCH*MTOK];
__device__ int   g_off  [BATCH*MTOK];
__device__ float g_yaca [ROWS*DIMC];
__device__ float g_ywin [ROWS*DIMC];
__device__ float g_xsum [ROWS*DIMC];
__device__ float g_x2n  [ROWS*DIMC];
__device__ float g_hc   [ROWS*CFF];
__device__ float g_hc2  [ROWS*CFF];
__device__ float g_wbias[HEADS*WINN*WINN];

// ---------------------------------------------------------------------------
// Helpers
// ---------------------------------------------------------------------------
__device__ __forceinline__ float warp_sum(float v) {
    #pragma unroll
    for (int o = 16; o; o >>= 1) v += __shfl_xor_sync(0xffffffffu, v, o);
    return v;
}
__device__ __forceinline__ float gelu_exact(float v) {
    return 0.5f * v * (1.0f + erff(v * 0.70710678118654752440f));
}

// ---------------------------------------------------------------------------
// LayerNorm: one warp per row of 180
// ---------------------------------------------------------------------------
__global__ void ln_kernel(const float* __restrict__ x, const float* __restrict__ g,
                          const float* __restrict__ b, float* __restrict__ out) {
    int row = (blockIdx.x * blockDim.x + threadIdx.x) >> 5;
    if (row >= ROWS) return;
    int lane = threadIdx.x & 31;
    const float* xr = x + (size_t)row * DIMC;
    float v[6], s = 0.f, s2 = 0.f;
    #pragma unroll
    for (int k = 0; k < 6; k++) {
        int c = lane + k * 32;
        v[k] = (c < DIMC) ? xr[c] : 0.f;
        s += v[k]; s2 += v[k] * v[k];
    }
    s = warp_sum(s); s2 = warp_sum(s2);
    float mu = s * (1.f / DIMC);
    float var = s2 * (1.f / DIMC) - mu * mu;
    float rstd = rsqrtf(var + 1e-5f);
    float* orow = out + (size_t)row * DIMC;
    #pragma unroll
    for (int k = 0; k < 6; k++) {
        int c = lane + k * 32;
        if (c < DIMC) orow[c] = (v[k] - mu) * rstd * g[c] + b[c];
    }
}

// ---------------------------------------------------------------------------
// Generic tiled GEMM: C = act( A1@W1 [+ A2@W2] + b1 [+ b2] [+ add1] [+ add2] )
// A row-major [M,K] (lda == K), W row-major [K,N]. BM=BN=64, BK=16.
// ---------------------------------------------------------------------------
__global__ void gemm_kernel(const float* __restrict__ A1, const float* __restrict__ W1, int K1,
                            const float* __restrict__ A2, const float* __restrict__ W2, int K2,
                            const float* __restrict__ b1, const float* __restrict__ b2,
                            const float* __restrict__ add1, const float* __restrict__ add2,
                            float* __restrict__ C, int M, int N, int ldc, int act) {
    __shared__ float As[16][68];
    __shared__ float Ws[16][68];
    int row0 = blockIdx.y * 64;
    int col0 = blockIdx.x * 64;
    int tid = threadIdx.x;
    int ty = tid >> 4, tx = tid & 15;
    float acc[4][4];
    #pragma unroll
    for (int i = 0; i < 4; i++)
        #pragma unroll
        for (int j = 0; j < 4; j++) acc[i][j] = 0.f;

    for (int pass = 0; pass < 2; ++pass) {
        const float* A = pass ? A2 : A1;
        const float* W = pass ? W2 : W1;
        int K = pass ? K2 : K1;
        if (K == 0 || A == nullptr) continue;
        for (int k0 = 0; k0 < K; k0 += 16) {
            #pragma unroll
            for (int i = 0; i < 4; i++) {
                int e = tid + i * 256;
                int m = e >> 4, kk = e & 15;
                int gk = k0 + kk;
                As[kk][m] = (gk < K) ? A[(size_t)(row0 + m) * K + gk] : 0.f;
            }
            #pragma unroll
            for (int i = 0; i < 4; i++) {
                int e = tid + i * 256;
                int kk = e >> 6, n = e & 63;
                int gk = k0 + kk, gn = col0 + n;
                Ws[kk][n] = (gk < K && gn < N) ? W[(size_t)gk * N + gn] : 0.f;
            }
            __syncthreads();
            #pragma unroll
            for (int kk = 0; kk < 16; kk++) {
                float4 a4 = *(const float4*)&As[kk][ty * 4];
                float4 w4 = *(const float4*)&Ws[kk][tx * 4];
                float aa[4] = {a4.x, a4.y, a4.z, a4.w};
                float ww[4] = {w4.x, w4.y, w4.z, w4.w};
                #pragma unroll
                for (int i = 0; i < 4; i++)
                    #pragma unroll
                    for (int j = 0; j < 4; j++) acc[i][j] += aa[i] * ww[j];
            }
            __syncthreads();
        }
    }

    #pragma unroll
    for (int mi = 0; mi < 4; mi++) {
        int r = row0 + ty * 4 + mi;
        #pragma unroll
        for (int ni = 0; ni < 4; ni++) {
            int c = col0 + tx * 4 + ni;
            if (c < N && r < M) {
                float v = acc[mi][ni];
                if (b1)   v += b1[c];
                if (b2)   v += b2[c];
                if (add1) v += add1[(size_t)r * N + c];
                if (add2) v += add2[(size_t)r * N + c];
                if (act)  v = gelu_exact(v);
                C[(size_t)r * ldc + c] = v;
            }
        }
    }
}

// ---------------------------------------------------------------------------
// Small GEMM: one block per A-row, smem-cached row. C[M,N] = A[M,K]@W[K,N]+b
// ---------------------------------------------------------------------------
__global__ void smallmm_kernel(const float* __restrict__ A, const float* __restrict__ W,
                               const float* __restrict__ bias, float* __restrict__ C,
                               int N, int K) {
    int r = blockIdx.x;
    __shared__ float as[192];
    const float* ar = A + (size_t)r * K;
    for (int k = threadIdx.x; k < K; k += blockDim.x) as[k] = ar[k];
    __syncthreads();
    for (int c = threadIdx.x; c < N; c += blockDim.x) {
        float acc = bias ? bias[c] : 0.f;
        for (int k = 0; k < K; k++) acc += as[k] * W[(size_t)k * N + c];
        C[(size_t)r * N + c] = acc;
    }
}

// l2-normalize rows of dim 10 (kk dictionary keys)
__global__ void l2norm10_kernel(float* __restrict__ d, int rows) {
    int r = (blockIdx.x * blockDim.x + threadIdx.x) >> 5;
    if (r >= rows) return;
    int lane = threadIdx.x & 31;
    float v = (lane < RDIM) ? d[(size_t)r * RDIM + lane] : 0.f;
    float ss = warp_sum(v * v);
    float inv = 1.f / fmaxf(sqrtf(ss), 1e-12f);
    if (lane < RDIM) d[(size_t)r * RDIM + lane] = v * inv;
}

// ---------------------------------------------------------------------------
// ATD cross-attention to token dictionary: one warp per token.
// ---------------------------------------------------------------------------
__global__ void atd_kernel(const float* __restrict__ qatd, const float* __restrict__ kkn,
                           const float* __restrict__ vv, const float* __restrict__ scale,
                           float* __restrict__ xatd, int* __restrict__ tkid) {
    int t = (blockIdx.x * blockDim.x + threadIdx.x) >> 5;
    int w = threadIdx.x >> 5;
    int lane = threadIdx.x & 31;
    __shared__ float psh[8][64];
    if (t >= ROWS) return;
    int b = t >> 12;
    float q = (lane < RDIM) ? qatd[(size_t)t * RDIM + lane] : 0.f;
    float ss = warp_sum(q * q);
    float qn = q * (1.f / fmaxf(sqrtf(ss), 1e-12f));
    const float* kb = kkn + (size_t)b * MTOK * RDIM;
    float s0 = 0.f, s1 = 0.f;
    #pragma unroll
    for (int d = 0; d < RDIM; d++) {
        float qd = __shfl_sync(0xffffffffu, qn, d);
        s0 += qd * kb[lane * RDIM + d];
        s1 += qd * kb[(lane + 32) * RDIM + d];
    }
    float sc = fminf(fmaxf(scale[0], 0.f), 3.f);
    float ls = 1.f + sc * 4.15888308335967186f;  // log(64)
    s0 *= ls; s1 *= ls;
    float mv = fmaxf(s0, s1);
    int mi = (s0 >= s1) ? lane : lane + 32;      // tie -> lower index
    #pragma unroll
    for (int o = 16; o; o >>= 1) {
        float ov = __shfl_xor_sync(0xffffffffu, mv, o);
        int   oi = __shfl_xor_sync(0xffffffffu, mi, o);
        if (ov > mv || (ov == mv && oi < mi)) { mv = ov; mi = oi; }
    }
    float p0 = __expf(s0 - mv), p1 = __expf(s1 - mv);
    float sum = warp_sum(p0 + p1);
    float inv = 1.f / sum;
    psh[w][lane] = p0 * inv;
    psh[w][lane + 32] = p1 * inv;
    __syncwarp();
    const float* vb = vv + (size_t)b * MTOK * DIMC;
    float* orow = xatd + (size_t)t * DIMC;
    for (int c = lane; c < DIMC; c += 32) {
        float a = 0.f;
        #pragma unroll 8
        for (int m = 0; m < MTOK; m++) a += psh[w][m] * vb[m * DIMC + c];
        orow[c] = a;
    }
    if (lane == 0) tkid[t] = mi;
}

// ---------------------------------------------------------------------------
// Stable counting sort of tk_id per batch
// ---------------------------------------------------------------------------
__global__ void zero_cnt_kernel() {
    if (threadIdx.x < BATCH * MTOK) g_cnt[threadIdx.x] = 0;
}
__global__ void hist_kernel(const int* __restrict__ tkid) {
    int i = blockIdx.x * blockDim.x + threadIdx.x;
    if (i < ROWS) atomicAdd(&g_cnt[(i >> 12) * MTOK + tkid[i]], 1);
}
__global__ void offs_kernel() {
    int b = threadIdx.x;
    if (b < BATCH) {
        int r = 0;
        for (int j = 0; j < MTOK; j++) { g_off[b * MTOK + j] = r; r += g_cnt[b * MTOK + j]; }
    }
}
__global__ void scatter_kernel(const int* __restrict__ tkid, int* __restrict__ sidx) {
    int b = blockIdx.x >> 6, bin = blockIdx.x & 63;
    const int* tk = tkid + b * NTOK;
    __shared__ int sc[256];
    int t = threadIdx.x;
    int start = t * 16;
    int cnt = 0;
    #pragma unroll
    for (int k = 0; k < 16; k++) cnt += (tk[start + k] == bin);
    sc[t] = cnt;
    __syncthreads();
    for (int d = 1; d < 256; d <<= 1) {
        int v = (t >= d) ? sc[t - d] : 0;
        __syncthreads();
        sc[t] += v;
        __syncthreads();
    }
    int pos = g_off[b * MTOK + bin] + sc[t] - cnt;
    for (int k = 0; k < 16; k++)
        if (tk[start + k] == bin) sidx[b * NTOK + pos++] = start + k;
}

// ---------------------------------------------------------------------------
// AC_MSA: grouped attention over sorted tokens. 1 block = (b, group, head),
// 128 threads = 128 queries. K/V in smem padded to 32 floats.
// ---------------------------------------------------------------------------
__global__ void acmsa_kernel(const float* __restrict__ qkv, const int* __restrict__ sidx,
                             float* __restrict__ yout) {
    int bi = blockIdx.x;
    int hh = bi % HEADS;
    int g  = (bi / HEADS) % NG;
    int b  = bi / (HEADS * NG);
    int t = threadIdx.x;
    __shared__ float Ks[GS][32], Vs[GS][32];
    int rn = sidx[b * NTOK + g * GS + t];
    const float* base = qkv + ((size_t)(b * NTOK + rn)) * QKVW + hh * HD;
    const float scale = 0.18257418583505536f;   // 30^-0.5
    float q[32];
    #pragma unroll
    for (int d = 0; d < HD; d++) {
        q[d] = base[d] * scale;
        Ks[t][d] = base[180 + d];
        Vs[t][d] = base[360 + d];
    }
    q[30] = q[31] = 0.f;
    Ks[t][30] = Ks[t][31] = 0.f;
    Vs[t][30] = Vs[t][31] = 0.f;
    __syncthreads();
    float m = -1e30f, l = 0.f, acc[32];
    #pragma unroll
    for (int d = 0; d < 32; d++) acc[d] = 0.f;
    for (int j = 0; j < GS; j++) {
        float s = 0.f;
        const float4* k4 = (const float4*)Ks[j];
        #pragma unroll
        for (int d = 0; d < 8; d++) {
            float4 kv = k4[d];
            s += q[d*4] * kv.x + q[d*4+1] * kv.y + q[d*4+2] * kv.z + q[d*4+3] * kv.w;
        }
        float mn = fmaxf(m, s);
        float co = __expf(m - mn);
        float p  = __expf(s - mn);
        l = l * co + p; m = mn;
        const float4* v4 = (const float4*)Vs[j];
        #pragma unroll
        for (int d = 0; d < 8; d++) {
            float4 vv_ = v4[d];
            acc[d*4]   = acc[d*4]   * co + p * vv_.x;
            acc[d*4+1] = acc[d*4+1] * co + p * vv_.y;
            acc[d*4+2] = acc[d*4+2] * co + p * vv_.z;
            acc[d*4+3] = acc[d*4+3] * co + p * vv_.w;
        }
    }
    float inv = 1.f / l;
    float* orow = yout + ((size_t)(b * NTOK + rn)) * DIMC + hh * HD;
    #pragma unroll
    for (int d = 0; d < HD; d++) orow[d] = acc[d] * inv;
}

// ---------------------------------------------------------------------------
// Window attention bias: bias[h][i][j] = rpb[rpi[i*256+j]*6 + h]
// ---------------------------------------------------------------------------
__global__ void wbias_kernel(const int* __restrict__ rpi, const float* __restrict__ rpb) {
    int e = blockIdx.x * blockDim.x + threadIdx.x;
    if (e < WINN * WINN) {
        int idx = rpi[e];
        #pragma unroll
        for (int h = 0; h < HEADS; h++) g_wbias[h * WINN * WINN + e] = rpb[idx * HEADS + h];
    }
}

// ---------------------------------------------------------------------------
// Window attention: 1 block = (window, head), 256 threads = 256 queries.
// Dynamic smem: K[256][32] + V[256][32] fp32 = 64 KiB.
// ---------------------------------------------------------------------------
__global__ void winattn_kernel(const float* __restrict__ qkv, float* __restrict__ yout) {
    extern __shared__ float sm[];
    float* Ks = sm;
    float* Vs = sm + WINN * 32;
    int bi = blockIdx.x;
    int hh = bi % HEADS;
    int wdx = bi / HEADS;            // 0..127
    int b = wdx >> 4;
    int wy = (wdx >> 2) & 3;
    int wx = wdx & 3;
    int t = threadIdx.x;             // query index within window
    int iy = t >> 4, ix = t & 15;
    int nidx = (wy * WS + iy) * WW + (wx * WS + ix);
    size_t rowbase = ((size_t)(b * NTOK + nidx)) * QKVW + hh * HD;
    const float scale = 0.18257418583505536f;
    float q[32];
    #pragma unroll
    for (int d = 0; d < HD; d++) {
        q[d] = qkv[rowbase + d] * scale;
        Ks[t * 32 + d] = qkv[rowbase + 180 + d];
        Vs[t * 32 + d] = qkv[rowbase + 360 + d];
    }
    q[30] = q[31] = 0.f;
    Ks[t * 32 + 30] = Ks[t * 32 + 31] = 0.f;
    Vs[t * 32 + 30] = Vs[t * 32 + 31] = 0.f;
    __syncthreads();
    const float* brow = g_wbias + ((size_t)hh * WINN + t) * WINN;
    float m = -1e30f, l = 0.f, acc[32];
    #pragma unroll
    for (int d = 0; d < 32; d++) acc[d] = 0.f;
    for (int j = 0; j < WINN; j++) {
        float s = brow[j];
        const float4* k4 = (const float4*)(Ks + j * 32);
        #pragma unroll
        for (int d = 0; d < 8; d++) {
            float4 kv = k4[d];
            s += q[d*4] * kv.x + q[d*4+1] * kv.y + q[d*4+2] * kv.z + q[d*4+3] * kv.w;
        }
        float mn = fmaxf(m, s);
        float co = __expf(m - mn);
        float p  = __expf(s - mn);
        l = l * co + p; m = mn;
        const float4* v4 = (const float4*)(Vs + j * 32);
        #pragma unroll
        for (int d = 0; d < 8; d++) {
            float4 vv_ = v4[d];
            acc[d*4]   = acc[d*4]   * co + p * vv_.x;
            acc[d*4+1] = acc[d*4+1] * co + p * vv_.y;
            acc[d*4+2] = acc[d*4+2] * co + p * vv_.z;
            acc[d*4+3] = acc[d*4+3] * co + p * vv_.w;
        }
    }
    float inv = 1.f / l;
    float* orow = yout + ((size_t)(b * NTOK + nidx)) * DIMC + hh * HD;
    #pragma unroll
    for (int d = 0; d < HD; d++) orow[d] = acc[d] * inv;
}

// ---------------------------------------------------------------------------
// Gather per-token dictionary features into hc[:, 360:424]
// ---------------------------------------------------------------------------
__global__ void gathertd_kernel(const float* __restrict__ tdproj, const int* __restrict__ tkid,
                                float* __restrict__ hc) {
    int e = blockIdx.x * blockDim.x + threadIdx.x;
    if (e < ROWS * DTD) {
        int r = e >> 6, j = e & 63;
        int b = r >> 12;
        hc[(size_t)r * CFF + MLP_HID + j] = tdproj[((size_t)b * MTOK + tkid[r]) * DTD + j];
    }
}

// ---------------------------------------------------------------------------
// Depthwise 5x5 conv (SAME, cross-correlation) + GELU + residual into hc2
// ---------------------------------------------------------------------------
__global__ void dwconv_kernel(const float* __restrict__ hc, const float* __restrict__ w,
                              const float* __restrict__ bias, float* __restrict__ hc2) {
    int pix = blockIdx.x;               // 0..32767
    int b = pix >> 12;
    int n = pix & 4095;
    int y = n >> 6, x = n & 63;
    for (int c = threadIdx.x; c < CFF; c += blockDim.x) {
        float acc = 0.f;
        #pragma unroll
        for (int ky = 0; ky < 5; ky++) {
            int yy = y + ky - 2;
            if (yy < 0 || yy > 63) continue;
            #pragma unroll
            for (int kx = 0; kx < 5; kx++) {
                int xx = x + kx - 2;
                if (xx < 0 || xx > 63) continue;
                acc += hc[(((size_t)b * NTOK) + (yy * WW + xx)) * CFF + c] * w[c * 25 + ky * 5 + kx];
            }
        }
        float g = gelu_exact(acc + bias[c]);
        size_t idx = (size_t)pix * CFF + c;
        hc2[idx] = hc[idx] + g;
    }
}

// ---------------------------------------------------------------------------
// Launch
// ---------------------------------------------------------------------------
extern "C" void kernel_launch(void* const* d_in, const int* in_sizes, int n_in,
                              void* d_out, int out_size) {
    const float* x        = (const float*)d_in[0];
    const float* td       = (const float*)d_in[1];
    const float* n1g      = (const float*)d_in[2];
    const float* n1b      = (const float*)d_in[3];
    const float* wqkv_w   = (const float*)d_in[4];
    const float* wqkv_b   = (const float*)d_in[5];
    const float* atd_wq_w = (const float*)d_in[6];
    const float* atd_wq_b = (const float*)d_in[7];
    const float* atd_wk_w = (const float*)d_in[8];
    const float* atd_wk_b = (const float*)d_in[9];
    const float* atd_wv_w = (const float*)d_in[10];
    const float* atd_wv_b = (const float*)d_in[11];
    const float* atd_sc   = (const float*)d_in[12];
    const float* aca_w    = (const float*)d_in[13];
    const float* aca_b    = (const float*)d_in[14];
    const float* win_rpb  = (const float*)d_in[15];
    const float* win_w    = (const float*)d_in[16];
    const float* win_b    = (const float*)d_in[17];
    const float* fctd_w   = (const float*)d_in[18];
    const float* fctd_b   = (const float*)d_in[19];
    const float* fc1_w    = (const float*)d_in[20];
    const float* fc1_b    = (const float*)d_in[21];
    const float* dw_w     = (const float*)d_in[22];
    const float* dw_b     = (const float*)d_in[23];
    const float* fc2_w    = (const float*)d_in[24];
    const float* fc2_b    = (const float*)d_in[25];
    const float* n2g      = (const float*)d_in[26];
    const float* n2b      = (const float*)d_in[27];
    const int*   rpi      = (const int*)d_in[28];
    float* out = (float*)d_out;

    float *xn, *qkv, *qatd, *kkn, *vv, *tdpr, *xatd, *yaca, *ywin, *xsum, *x2n, *hc, *hc2;
    int *tkid, *sidx;
    cudaGetSymbolAddress((void**)&xn,   g_xn);
    cudaGetSymbolAddress((void**)&qkv,  g_qkv);
    cudaGetSymbolAddress((void**)&qatd, g_qatd);
    cudaGetSymbolAddress((void**)&kkn,  g_kkn);
    cudaGetSymbolAddress((void**)&vv,   g_vv);
    cudaGetSymbolAddress((void**)&tdpr, g_tdpr);
    cudaGetSymbolAddress((void**)&xatd, g_xatd);
    cudaGetSymbolAddress((void**)&yaca, g_yaca);
    cudaGetSymbolAddress((void**)&ywin, g_ywin);
    cudaGetSymbolAddress((void**)&xsum, g_xsum);
    cudaGetSymbolAddress((void**)&x2n,  g_x2n);
    cudaGetSymbolAddress((void**)&hc,   g_hc);
    cudaGetSymbolAddress((void**)&hc2,  g_hc2);
    cudaGetSymbolAddress((void**)&tkid, g_tkid);
    cudaGetSymbolAddress((void**)&sidx, g_sidx);

    // 1. LN1
    ln_kernel<<<ROWS/8, 256>>>(x, n1g, n1b, xn);
    // 2. qkv = xn @ wqkv + b
    gemm_kernel<<<dim3(9, ROWS/64), 256>>>(xn, wqkv_w, DIMC, nullptr, nullptr, 0,
                                           wqkv_b, nullptr, nullptr, nullptr,
                                           qkv, ROWS, QKVW, QKVW, 0);
    // 3. q_atd = xn @ wq + b
    smallmm_kernel<<<ROWS, 32>>>(xn, atd_wq_w, atd_wq_b, qatd, RDIM, DIMC);
    // 4. dictionary projections
    smallmm_kernel<<<BATCH*MTOK, 32>>>(td, atd_wk_w, atd_wk_b, kkn, RDIM, DIMC);
    l2norm10_kernel<<<(BATCH*MTOK + 7)/8, 256>>>(kkn, BATCH*MTOK);
    smallmm_kernel<<<BATCH*MTOK, 192>>>(td, atd_wv_w, atd_wv_b, vv, DIMC, DIMC);
    smallmm_kernel<<<BATCH*MTOK, 64>>>(td, fctd_w, fctd_b, tdpr, DTD, DIMC);
    // 5. ATD attention + tk_id
    atd_kernel<<<ROWS/8, 256>>>(qatd, kkn, vv, atd_sc, xatd, tkid);
    // 6-8. stable counting sort of tk_id
    zero_cnt_kernel<<<1, 512>>>();
    hist_kernel<<<ROWS/256, 256>>>(tkid);
    offs_kernel<<<1, 8>>>();
    scatter_kernel<<<BATCH*MTOK, 256>>>(tkid, sidx);
    // 9. grouped attention (scatter output through sort_idx)
    acmsa_kernel<<<BATCH*NG*HEADS, 128>>>(qkv, sidx, yaca);
    // 10-11. window attention
    wbias_kernel<<<WINN*WINN/256, 256>>>(rpi, win_rpb);
    cudaFuncSetAttribute(winattn_kernel, cudaFuncAttributeMaxDynamicSharedMemorySize, 65536);
    winattn_kernel<<<NWIN*HEADS, 256, 65536>>>(qkv, ywin);
    // 12. xsum = x + x_atd + yaca@aca_w + aca_b + ywin@win_w + win_b
    gemm_kernel<<<dim3(3, ROWS/64), 256>>>(yaca, aca_w, DIMC, ywin, win_w, DIMC,
                                           aca_b, win_b, x, xatd,
                                           xsum, ROWS, DIMC, DIMC, 0);
    // 13. LN2
    ln_kernel<<<ROWS/8, 256>>>(xsum, n2g, n2b, x2n);
    // 14. fc1 + GELU into hc[:, 0:360]
    gemm_kernel<<<dim3(6, ROWS/64), 256>>>(x2n, fc1_w, DIMC, nullptr, nullptr, 0,
                                           fc1_b, nullptr, nullptr, nullptr,
                                           hc, ROWS, MLP_HID, CFF, 1);
    // 15. gather td features into hc[:, 360:424]
    gathertd_kernel<<<ROWS*DTD/256, 256>>>(tdpr, tkid, hc);
    // 16. depthwise conv + gelu + residual
    dwconv_kernel<<<ROWS, 256>>>(hc, dw_w, dw_b, hc2);
    // 17. out = xsum + hc2 @ fc2_w + fc2_b
    gemm_kernel<<<dim3(3, ROWS/64), 256>>>(hc2, fc2_w, CFF, nullptr, nullptr, 0,
                                           fc2_b, nullptr, xsum, nullptr,
                                           out, ROWS, DIMC, DIMC, 0);
}

// round 2
// speedup vs baseline: 1.1646x; 1.1646x over previous
#include <cuda_runtime.h>
#include <cuda_bf16.h>
#include <math.h>

// ---------------------------------------------------------------------------
// Problem constants
// ---------------------------------------------------------------------------
#define BATCH 8
#define NTOK 4096
#define ROWS (BATCH*NTOK)
#define DIMC 180
#define HEADS 6
#define HD 30
#define QKVW 540
#define MTOK 64
#define RDIM 10
#define GS 128
#define NG 32
#define WS 16
#define WINN 256
#define NWIN 128
#define MLP_HID 360
#define DTD 64
#define CFF 424
#define HH 64
#define WW 64

// ---------------------------------------------------------------------------
// Scratch
// ---------------------------------------------------------------------------
__device__ float g_xn   [ROWS*DIMC];
__device__ float g_qkv  [ROWS*QKVW];
__device__ float g_qatd [ROWS*RDIM];
__device__ float g_kkn  [BATCH*MTOK*RDIM];
__device__ float g_vv   [BATCH*MTOK*DIMC];
__device__ float g_tdpr [BATCH*MTOK*DTD];
__device__ float g_xatd [ROWS*DIMC];
__device__ int   g_tkid [ROWS];
__device__ int   g_sidx [ROWS];
__device__ int   g_cnt  [BATCH*MTOK];
__device__ int   g_off  [BATCH*MTOK];
__device__ float g_yaca [ROWS*DIMC];
__device__ float g_ywin [ROWS*DIMC];
__device__ float g_xsum [ROWS*DIMC];
__device__ float g_x2n  [ROWS*DIMC];
__device__ float g_hc   [ROWS*CFF];
__device__ float g_hc2  [ROWS*CFF];
__device__ float g_wbias[HEADS*WINN*WINN];

// ---------------------------------------------------------------------------
// Helpers
// ---------------------------------------------------------------------------
__device__ __forceinline__ float warp_sum(float v) {
    #pragma unroll
    for (int o = 16; o; o >>= 1) v += __shfl_xor_sync(0xffffffffu, v, o);
    return v;
}
__device__ __forceinline__ float gelu_exact(float v) {
    return 0.5f * v * (1.0f + erff(v * 0.70710678118654752440f));
}
__device__ __forceinline__ unsigned f2tf32(float v) {
    unsigned u;
    asm("cvt.rna.tf32.f32 %0, %1;" : "=r"(u) : "f"(v));
    return u;
}

// ---------------------------------------------------------------------------
// LayerNorm: one warp per row of 180
// ---------------------------------------------------------------------------
__global__ void ln_kernel(const float* __restrict__ x, const float* __restrict__ g,
                          const float* __restrict__ b, float* __restrict__ out) {
    int row = (blockIdx.x * blockDim.x + threadIdx.x) >> 5;
    if (row >= ROWS) return;
    int lane = threadIdx.x & 31;
    const float* xr = x + (size_t)row * DIMC;
    float v[6], s = 0.f, s2 = 0.f;
    #pragma unroll
    for (int k = 0; k < 6; k++) {
        int c = lane + k * 32;
        v[k] = (c < DIMC) ? xr[c] : 0.f;
        s += v[k]; s2 += v[k] * v[k];
    }
    s = warp_sum(s); s2 = warp_sum(s2);
    float mu = s * (1.f / DIMC);
    float var = s2 * (1.f / DIMC) - mu * mu;
    float rstd = rsqrtf(var + 1e-5f);
    float* orow = out + (size_t)row * DIMC;
    #pragma unroll
    for (int k = 0; k < 6; k++) {
        int c = lane + k * 32;
        if (c < DIMC) orow[c] = (v[k] - mu) * rstd * g[c] + b[c];
    }
}

// ---------------------------------------------------------------------------
// Tensor-core tf32 GEMM: C = act( A1@W1 [+ A2@W2] + b1 [+ b2] [+add1] [+add2] )
// A row-major [M,K], W row-major [K,N]. BM=128, BN=64, BK=16, 256 threads.
// Warp grid 4(M) x 2(N); each warp owns a 32x32 tile = 2x4 m16n8 mma tiles.
// M must be a multiple of 128 (always true here: 32768).
// ---------------------------------------------------------------------------
__global__ void gemm_tc(const float* __restrict__ A1, const float* __restrict__ W1, int K1,
                        const float* __restrict__ A2, const float* __restrict__ W2, int K2,
                        const float* __restrict__ b1, const float* __restrict__ b2,
                        const float* __restrict__ add1, const float* __restrict__ add2,
                        float* __restrict__ C, int M, int N, int ldc, int act) {
    __shared__ float As[16][132];   // [k][m]
    __shared__ float Ws[16][68];    // [k][n]
    int tid  = threadIdx.x;
    int lane = tid & 31;
    int warp = tid >> 5;
    int warpM = warp & 3;           // 0..3
    int warpN = warp >> 2;          // 0..1
    int gId = lane >> 2;            // 0..7
    int tig = lane & 3;             // 0..3
    int row0 = blockIdx.y * 128;
    int col0 = blockIdx.x * 64;

    float d[2][4][4];
    #pragma unroll
    for (int mt = 0; mt < 2; mt++)
        #pragma unroll
        for (int nt = 0; nt < 4; nt++)
            #pragma unroll
            for (int i = 0; i < 4; i++) d[mt][nt][i] = 0.f;

    for (int pass = 0; pass < 2; ++pass) {
        const float* A = pass ? A2 : A1;
        const float* W = pass ? W2 : W1;
        int K = pass ? K2 : K1;
        if (K == 0 || A == nullptr) continue;
        int ktiles = (K + 15) >> 4;
        for (int kt = 0; kt < ktiles; kt++) {
            int k0 = kt << 4;
            // --- load A tile 128x16 into As[k][m]; 2 float4 per thread ---
            #pragma unroll
            for (int f = 0; f < 2; f++) {
                int e = tid * 2 + f;          // 0..511
                int m = e >> 2;               // 0..127
                int kk = (e & 3) << 2;        // 0,4,8,12
                int gk = k0 + kk;
                const float* ap = A + (size_t)(row0 + m) * K + gk;
                float4 v;
                if (gk + 3 < K) v = *(const float4*)ap;
                else {
                    v.x = (gk   < K) ? ap[0] : 0.f;
                    v.y = (gk+1 < K) ? ap[1] : 0.f;
                    v.z = (gk+2 < K) ? ap[2] : 0.f;
                    v.w = (gk+3 < K) ? ap[3] : 0.f;
                }
                As[kk  ][m] = __uint_as_float(f2tf32(v.x));
                As[kk+1][m] = __uint_as_float(f2tf32(v.y));
                As[kk+2][m] = __uint_as_float(f2tf32(v.z));
                As[kk+3][m] = __uint_as_float(f2tf32(v.w));
            }
            // --- load W tile 16x64 into Ws[k][n]; 1 float4 per thread ---
            {
                int kk = tid >> 4;            // 0..15
                int n4 = (tid & 15) << 2;     // 0..60
                int gk = k0 + kk;
                int gn = col0 + n4;
                float4 v = {0.f, 0.f, 0.f, 0.f};
                if (gk < K) {
                    const float* wp = W + (size_t)gk * N + gn;
                    if (gn + 3 < N) v = *(const float4*)wp;
                    else {
                        if (gn   < N) v.x = wp[0];
                        if (gn+1 < N) v.y = wp[1];
                        if (gn+2 < N) v.z = wp[2];
                        if (gn+3 < N) v.w = wp[3];
                    }
                }
                Ws[kk][n4  ] = __uint_as_float(f2tf32(v.x));
                Ws[kk][n4+1] = __uint_as_float(f2tf32(v.y));
                Ws[kk][n4+2] = __uint_as_float(f2tf32(v.z));
                Ws[kk][n4+3] = __uint_as_float(f2tf32(v.w));
            }
            __syncthreads();
            // --- 2 k8 steps ---
            #pragma unroll
            for (int ks = 0; ks < 2; ks++) {
                int kb = ks * 8;
                unsigned a[2][4], bfr[4][2];
                #pragma unroll
                for (int mt = 0; mt < 2; mt++) {
                    int m0 = warpM * 32 + mt * 16;
                    a[mt][0] = __float_as_uint(As[kb + tig    ][m0 + gId]);
                    a[mt][1] = __float_as_uint(As[kb + tig    ][m0 + gId + 8]);
                    a[mt][2] = __float_as_uint(As[kb + tig + 4][m0 + gId]);
                    a[mt][3] = __float_as_uint(As[kb + tig + 4][m0 + gId + 8]);
                }
                #pragma unroll
                for (int nt = 0; nt < 4; nt++) {
                    int n0 = warpN * 32 + nt * 8;
                    bfr[nt][0] = __float_as_uint(Ws[kb + tig    ][n0 + gId]);
                    bfr[nt][1] = __float_as_uint(Ws[kb + tig + 4][n0 + gId]);
                }
                #pragma unroll
                for (int mt = 0; mt < 2; mt++)
                    #pragma unroll
                    for (int nt = 0; nt < 4; nt++) {
                        asm volatile(
                            "mma.sync.aligned.m16n8k8.row.col.f32.tf32.tf32.f32 "
                            "{%0,%1,%2,%3},{%4,%5,%6,%7},{%8,%9},{%0,%1,%2,%3};"
                            : "+f"(d[mt][nt][0]), "+f"(d[mt][nt][1]),
                              "+f"(d[mt][nt][2]), "+f"(d[mt][nt][3])
                            : "r"(a[mt][0]), "r"(a[mt][1]), "r"(a[mt][2]), "r"(a[mt][3]),
                              "r"(bfr[nt][0]), "r"(bfr[nt][1]));
                    }
            }
            __syncthreads();
        }
    }

    // --- epilogue ---
    #pragma unroll
    for (int mt = 0; mt < 2; mt++) {
        #pragma unroll
        for (int nt = 0; nt < 4; nt++) {
            #pragma unroll
            for (int i = 0; i < 4; i++) {
                int r = row0 + warpM * 32 + mt * 16 + gId + (i >> 1) * 8;
                int c = col0 + warpN * 32 + nt * 8 + tig * 2 + (i & 1);
                if (c < N) {
                    float v = d[mt][nt][i];
                    if (b1)   v += b1[c];
                    if (b2)   v += b2[c];
                    if (add1) v += add1[(size_t)r * N + c];
                    if (add2) v += add2[(size_t)r * N + c];
                    if (act)  v = gelu_exact(v);
                    C[(size_t)r * ldc + c] = v;
                }
            }
        }
    }
}

// ---------------------------------------------------------------------------
// Small GEMM: one block per A-row
// ---------------------------------------------------------------------------
__global__ void smallmm_kernel(const float* __restrict__ A, const float* __restrict__ W,
                               const float* __restrict__ bias, float* __restrict__ C,
                               int N, int K) {
    int r = blockIdx.x;
    __shared__ float as[448];
    const float* ar = A + (size_t)r * K;
    for (int k = threadIdx.x; k < K; k += blockDim.x) as[k] = ar[k];
    __syncthreads();
    for (int c = threadIdx.x; c < N; c += blockDim.x) {
        float acc = bias ? bias[c] : 0.f;
        for (int k = 0; k < K; k++) acc += as[k] * W[(size_t)k * N + c];
        C[(size_t)r * N + c] = acc;
    }
}

__global__ void l2norm10_kernel(float* __restrict__ d, int rows) {
    int r = (blockIdx.x * blockDim.x + threadIdx.x) >> 5;
    if (r >= rows) return;
    int lane = threadIdx.x & 31;
    float v = (lane < RDIM) ? d[(size_t)r * RDIM + lane] : 0.f;
    float ss = warp_sum(v * v);
    float inv = 1.f / fmaxf(sqrtf(ss), 1e-12f);
    if (lane < RDIM) d[(size_t)r * RDIM + lane] = v * inv;
}

// ---------------------------------------------------------------------------
// ATD cross-attention: one warp per token
// ---------------------------------------------------------------------------
__global__ void atd_kernel(const float* __restrict__ qatd, const float* __restrict__ kkn,
                           const float* __restrict__ vv, const float* __restrict__ scale,
                           float* __restrict__ xatd, int* __restrict__ tkid) {
    int t = (blockIdx.x * blockDim.x + threadIdx.x) >> 5;
    int w = threadIdx.x >> 5;
    int lane = threadIdx.x & 31;
    __shared__ float psh[8][64];
    if (t >= ROWS) return;
    int b = t >> 12;
    float q = (lane < RDIM) ? qatd[(size_t)t * RDIM + lane] : 0.f;
    float ss = warp_sum(q * q);
    float qn = q * (1.f / fmaxf(sqrtf(ss), 1e-12f));
    const float* kb = kkn + (size_t)b * MTOK * RDIM;
    float s0 = 0.f, s1 = 0.f;
    #pragma unroll
    for (int d = 0; d < RDIM; d++) {
        float qd = __shfl_sync(0xffffffffu, qn, d);
        s0 += qd * kb[lane * RDIM + d];
        s1 += qd * kb[(lane + 32) * RDIM + d];
    }
    float sc = fminf(fmaxf(scale[0], 0.f), 3.f);
    float ls = 1.f + sc * 4.15888308335967186f;
    s0 *= ls; s1 *= ls;
    float mv = fmaxf(s0, s1);
    int mi = (s0 >= s1) ? lane : lane + 32;
    #pragma unroll
    for (int o = 16; o; o >>= 1) {
        float ov = __shfl_xor_sync(0xffffffffu, mv, o);
        int   oi = __shfl_xor_sync(0xffffffffu, mi, o);
        if (ov > mv || (ov == mv && oi < mi)) { mv = ov; mi = oi; }
    }
    float p0 = __expf(s0 - mv), p1 = __expf(s1 - mv);
    float sum = warp_sum(p0 + p1);
    float inv = 1.f / sum;
    psh[w][lane] = p0 * inv;
    psh[w][lane + 32] = p1 * inv;
    __syncwarp();
    const float* vb = vv + (size_t)b * MTOK * DIMC;
    float* orow = xatd + (size_t)t * DIMC;
    for (int c = lane; c < DIMC; c += 32) {
        float a = 0.f;
        #pragma unroll 8
        for (int m = 0; m < MTOK; m++) a += psh[w][m] * vb[m * DIMC + c];
        orow[c] = a;
    }
    if (lane == 0) tkid[t] = mi;
}

// ---------------------------------------------------------------------------
// Stable counting sort of tk_id per batch
// ---------------------------------------------------------------------------
__global__ void zero_cnt_kernel() {
    if (threadIdx.x < BATCH * MTOK) g_cnt[threadIdx.x] = 0;
}
__global__ void hist_kernel(const int* __restrict__ tkid) {
    int i = blockIdx.x * blockDim.x + threadIdx.x;
    if (i < ROWS) atomicAdd(&g_cnt[(i >> 12) * MTOK + tkid[i]], 1);
}
__global__ void offs_kernel() {
    int b = threadIdx.x;
    if (b < BATCH) {
        int r = 0;
        for (int j = 0; j < MTOK; j++) { g_off[b * MTOK + j] = r; r += g_cnt[b * MTOK + j]; }
    }
}
__global__ void scatter_kernel(const int* __restrict__ tkid, int* __restrict__ sidx) {
    int b = blockIdx.x >> 6, bin = blockIdx.x & 63;
    const int* tk = tkid + b * NTOK;
    __shared__ int sc[256];
    int t = threadIdx.x;
    int start = t * 16;
    int cnt = 0;
    #pragma unroll
    for (int k = 0; k < 16; k++) cnt += (tk[start + k] == bin);
    sc[t] = cnt;
    __syncthreads();
    for (int d = 1; d < 256; d <<= 1) {
        int v = (t >= d) ? sc[t - d] : 0;
        __syncthreads();
        sc[t] += v;
        __syncthreads();
    }
    int pos = g_off[b * MTOK + bin] + sc[t] - cnt;
    for (int k = 0; k < 16; k++)
        if (tk[start + k] == bin) sidx[b * NTOK + pos++] = start + k;
}

// ---------------------------------------------------------------------------
// AC_MSA grouped attention
// ---------------------------------------------------------------------------
__global__ void acmsa_kernel(const float* __restrict__ qkv, const int* __restrict__ sidx,
                             float* __restrict__ yout) {
    int bi = blockIdx.x;
    int hh = bi % HEADS;
    int g  = (bi / HEADS) % NG;
    int b  = bi / (HEADS * NG);
    int t = threadIdx.x;
    __shared__ float Ks[GS][32], Vs[GS][32];
    int rn = sidx[b * NTOK + g * GS + t];
    const float* base = qkv + ((size_t)(b * NTOK + rn)) * QKVW + hh * HD;
    const float scale = 0.18257418583505536f;
    float q[32];
    #pragma unroll
    for (int d = 0; d < HD; d++) {
        q[d] = base[d] * scale;
        Ks[t][d] = base[180 + d];
        Vs[t][d] = base[360 + d];
    }
    q[30] = q[31] = 0.f;
    Ks[t][30] = Ks[t][31] = 0.f;
    Vs[t][30] = Vs[t][31] = 0.f;
    __syncthreads();
    float m = -1e30f, l = 0.f, acc[32];
    #pragma unroll
    for (int d = 0; d < 32; d++) acc[d] = 0.f;
    for (int j = 0; j < GS; j++) {
        float s = 0.f;
        const float4* k4 = (const float4*)Ks[j];
        #pragma unroll
        for (int d = 0; d < 8; d++) {
            float4 kv = k4[d];
            s += q[d*4] * kv.x + q[d*4+1] * kv.y + q[d*4+2] * kv.z + q[d*4+3] * kv.w;
        }
        float mn = fmaxf(m, s);
        float co = __expf(m - mn);
        float p  = __expf(s - mn);
        l = l * co + p; m = mn;
        const float4* v4 = (const float4*)Vs[j];
        #pragma unroll
        for (int d = 0; d < 8; d++) {
            float4 vv_ = v4[d];
            acc[d*4]   = acc[d*4]   * co + p * vv_.x;
            acc[d*4+1] = acc[d*4+1] * co + p * vv_.y;
            acc[d*4+2] = acc[d*4+2] * co + p * vv_.z;
            acc[d*4+3] = acc[d*4+3] * co + p * vv_.w;
        }
    }
    float inv = 1.f / l;
    float* orow = yout + ((size_t)(b * NTOK + rn)) * DIMC + hh * HD;
    #pragma unroll
    for (int d = 0; d < HD; d++) orow[d] = acc[d] * inv;
}

// ---------------------------------------------------------------------------
// Window attention bias expansion
// ---------------------------------------------------------------------------
__global__ void wbias_kernel(const int* __restrict__ rpi, const float* __restrict__ rpb) {
    int e = blockIdx.x * blockDim.x + threadIdx.x;
    if (e < WINN * WINN) {
        int idx = rpi[e];
        #pragma unroll
        for (int h = 0; h < HEADS; h++) g_wbias[h * WINN * WINN + e] = rpb[idx * HEADS + h];
    }
}

// ---------------------------------------------------------------------------
// Window attention
// ---------------------------------------------------------------------------
__global__ void winattn_kernel(const float* __restrict__ qkv, float* __restrict__ yout) {
    extern __shared__ float sm[];
    float* Ks = sm;
    float* Vs = sm + WINN * 32;
    int bi = blockIdx.x;
    int hh = bi % HEADS;
    int wdx = bi / HEADS;
    int b = wdx >> 4;
    int wy = (wdx >> 2) & 3;
    int wx = wdx & 3;
    int t = threadIdx.x;
    int iy = t >> 4, ix = t & 15;
    int nidx = (wy * WS + iy) * WW + (wx * WS + ix);
    size_t rowbase = ((size_t)(b * NTOK + nidx)) * QKVW + hh * HD;
    const float scale = 0.18257418583505536f;
    float q[32];
    #pragma unroll
    for (int d = 0; d < HD; d++) {
        q[d] = qkv[rowbase + d] * scale;
        Ks[t * 32 + d] = qkv[rowbase + 180 + d];
        Vs[t * 32 + d] = qkv[rowbase + 360 + d];
    }
    q[30] = q[31] = 0.f;
    Ks[t * 32 + 30] = Ks[t * 32 + 31] = 0.f;
    Vs[t * 32 + 30] = Vs[t * 32 + 31] = 0.f;
    __syncthreads();
    const float* brow = g_wbias + ((size_t)hh * WINN + t) * WINN;
    float m = -1e30f, l = 0.f, acc[32];
    #pragma unroll
    for (int d = 0; d < 32; d++) acc[d] = 0.f;
    for (int j = 0; j < WINN; j++) {
        float s = brow[j];
        const float4* k4 = (const float4*)(Ks + j * 32);
        #pragma unroll
        for (int d = 0; d < 8; d++) {
            float4 kv = k4[d];
            s += q[d*4] * kv.x + q[d*4+1] * kv.y + q[d*4+2] * kv.z + q[d*4+3] * kv.w;
        }
        float mn = fmaxf(m, s);
        float co = __expf(m - mn);
        float p  = __expf(s - mn);
        l = l * co + p; m = mn;
        const float4* v4 = (const float4*)(Vs + j * 32);
        #pragma unroll
        for (int d = 0; d < 8; d++) {
            float4 vv_ = v4[d];
            acc[d*4]   = acc[d*4]   * co + p * vv_.x;
            acc[d*4+1] = acc[d*4+1] * co + p * vv_.y;
            acc[d*4+2] = acc[d*4+2] * co + p * vv_.z;
            acc[d*4+3] = acc[d*4+3] * co + p * vv_.w;
        }
    }
    float inv = 1.f / l;
    float* orow = yout + ((size_t)(b * NTOK + nidx)) * DIMC + hh * HD;
    #pragma unroll
    for (int d = 0; d < HD; d++) orow[d] = acc[d] * inv;
}

// ---------------------------------------------------------------------------
// Gather per-token dictionary features into hc[:, 360:424]
// ---------------------------------------------------------------------------
__global__ void gathertd_kernel(const float* __restrict__ tdproj, const int* __restrict__ tkid,
                                float* __restrict__ hc) {
    int e = blockIdx.x * blockDim.x + threadIdx.x;
    if (e < ROWS * DTD) {
        int r = e >> 6, j = e & 63;
        int b = r >> 12;
        hc[(size_t)r * CFF + MLP_HID + j] = tdproj[((size_t)b * MTOK + tkid[r]) * DTD + j];
    }
}

// ---------------------------------------------------------------------------
// Depthwise 5x5 conv + GELU + residual
// ---------------------------------------------------------------------------
__global__ void dwconv_kernel(const float* __restrict__ hc, const float* __restrict__ w,
                              const float* __restrict__ bias, float* __restrict__ hc2) {
    int pix = blockIdx.x;
    int b = pix >> 12;
    int n = pix & 4095;
    int y = n >> 6, x = n & 63;
    for (int c = threadIdx.x; c < CFF; c += blockDim.x) {
        float acc = 0.f;
        #pragma unroll
        for (int ky = 0; ky < 5; ky++) {
            int yy = y + ky - 2;
            if (yy < 0 || yy > 63) continue;
            #pragma unroll
            for (int kx = 0; kx < 5; kx++) {
                int xx = x + kx - 2;
                if (xx < 0 || xx > 63) continue;
                acc += hc[(((size_t)b * NTOK) + (yy * WW + xx)) * CFF + c] * w[c * 25 + ky * 5 + kx];
            }
        }
        float g = gelu_exact(acc + bias[c]);
        size_t idx = (size_t)pix * CFF + c;
        hc2[idx] = hc[idx] + g;
    }
}

// ---------------------------------------------------------------------------
// Launch
// ---------------------------------------------------------------------------
extern "C" void kernel_launch(void* const* d_in, const int* in_sizes, int n_in,
                              void* d_out, int out_size) {
    const float* x        = (const float*)d_in[0];
    const float* td       = (const float*)d_in[1];
    const float* n1g      = (const float*)d_in[2];
    const float* n1b      = (const float*)d_in[3];
    const float* wqkv_w   = (const float*)d_in[4];
    const float* wqkv_b   = (const float*)d_in[5];
    const float* atd_wq_w = (const float*)d_in[6];
    const float* atd_wq_b = (const float*)d_in[7];
    const float* atd_wk_w = (const float*)d_in[8];
    const float* atd_wk_b = (const float*)d_in[9];
    const float* atd_wv_w = (const float*)d_in[10];
    const float* atd_wv_b = (const float*)d_in[11];
    const float* atd_sc   = (const float*)d_in[12];
    const float* aca_w    = (const float*)d_in[13];
    const float* aca_b    = (const float*)d_in[14];
    const float* win_rpb  = (const float*)d_in[15];
    const float* win_w    = (const float*)d_in[16];
    const float* win_b    = (const float*)d_in[17];
    const float* fctd_w   = (const float*)d_in[18];
    const float* fctd_b   = (const float*)d_in[19];
    const float* fc1_w    = (const float*)d_in[20];
    const float* fc1_b    = (const float*)d_in[21];
    const float* dw_w     = (const float*)d_in[22];
    const float* dw_b     = (const float*)d_in[23];
    const float* fc2_w    = (const float*)d_in[24];
    const float* fc2_b    = (const float*)d_in[25];
    const float* n2g      = (const float*)d_in[26];
    const float* n2b      = (const float*)d_in[27];
    const int*   rpi      = (const int*)d_in[28];
    float* out = (float*)d_out;

    float *xn, *qkv, *qatd, *kkn, *vv, *tdpr, *xatd, *yaca, *ywin, *xsum, *x2n, *hc, *hc2;
    int *tkid, *sidx;
    cudaGetSymbolAddress((void**)&xn,   g_xn);
    cudaGetSymbolAddress((void**)&qkv,  g_qkv);
    cudaGetSymbolAddress((void**)&qatd, g_qatd);
    cudaGetSymbolAddress((void**)&kkn,  g_kkn);
    cudaGetSymbolAddress((void**)&vv,   g_vv);
    cudaGetSymbolAddress((void**)&tdpr, g_tdpr);
    cudaGetSymbolAddress((void**)&xatd, g_xatd);
    cudaGetSymbolAddress((void**)&yaca, g_yaca);
    cudaGetSymbolAddress((void**)&ywin, g_ywin);
    cudaGetSymbolAddress((void**)&xsum, g_xsum);
    cudaGetSymbolAddress((void**)&x2n,  g_x2n);
    cudaGetSymbolAddress((void**)&hc,   g_hc);
    cudaGetSymbolAddress((void**)&hc2,  g_hc2);
    cudaGetSymbolAddress((void**)&tkid, g_tkid);
    cudaGetSymbolAddress((void**)&sidx, g_sidx);

    // 1. LN1
    ln_kernel<<<ROWS/8, 256>>>(x, n1g, n1b, xn);
    // 2. qkv = xn @ wqkv + b   (tensor core)
    gemm_tc<<<dim3(9, ROWS/128), 256>>>(xn, wqkv_w, DIMC, nullptr, nullptr, 0,
                                        wqkv_b, nullptr, nullptr, nullptr,
                                        qkv, ROWS, QKVW, QKVW, 0);
    // 3. q_atd = xn @ wq + b
    smallmm_kernel<<<ROWS, 32>>>(xn, atd_wq_w, atd_wq_b, qatd, RDIM, DIMC);
    // 4. dictionary projections
    smallmm_kernel<<<BATCH*MTOK, 32>>>(td, atd_wk_w, atd_wk_b, kkn, RDIM, DIMC);
    l2norm10_kernel<<<(BATCH*MTOK + 7)/8, 256>>>(kkn, BATCH*MTOK);
    smallmm_kernel<<<BATCH*MTOK, 192>>>(td, atd_wv_w, atd_wv_b, vv, DIMC, DIMC);
    smallmm_kernel<<<BATCH*MTOK, 64>>>(td, fctd_w, fctd_b, tdpr, DTD, DIMC);
    // 5. ATD attention + tk_id
    atd_kernel<<<ROWS/8, 256>>>(qatd, kkn, vv, atd_sc, xatd, tkid);
    // 6-8. stable counting sort of tk_id
    zero_cnt_kernel<<<1, 512>>>();
    hist_kernel<<<ROWS/256, 256>>>(tkid);
    offs_kernel<<<1, 8>>>();
    scatter_kernel<<<BATCH*MTOK, 256>>>(tkid, sidx);
    // 9. grouped attention
    acmsa_kernel<<<BATCH*NG*HEADS, 128>>>(qkv, sidx, yaca);
    // 10-11. window attention
    wbias_kernel<<<WINN*WINN/256, 256>>>(rpi, win_rpb);
    cudaFuncSetAttribute(winattn_kernel, cudaFuncAttributeMaxDynamicSharedMemorySize, 65536);
    winattn_kernel<<<NWIN*HEADS, 256, 65536>>>(qkv, ywin);
    // 12. xsum = x + x_atd + yaca@aca_w + aca_b + ywin@win_w + win_b
    gemm_tc<<<dim3(3, ROWS/128), 256>>>(yaca, aca_w, DIMC, ywin, win_w, DIMC,
                                        aca_b, win_b, x, xatd,
                                        xsum, ROWS, DIMC, DIMC, 0);
    // 13. LN2
    ln_kernel<<<ROWS/8, 256>>>(xsum, n2g, n2b, x2n);
    // 14. fc1 + GELU into hc[:, 0:360]
    gemm_tc<<<dim3(6, ROWS/128), 256>>>(x2n, fc1_w, DIMC, nullptr, nullptr, 0,
                                        fc1_b, nullptr, nullptr, nullptr,
                                        hc, ROWS, MLP_HID, CFF, 1);
    // 15. gather td features into hc[:, 360:424]
    gathertd_kernel<<<ROWS*DTD/256, 256>>>(tdpr, tkid, hc);
    // 16. depthwise conv + gelu + residual
    dwconv_kernel<<<ROWS, 256>>>(hc, dw_w, dw_b, hc2);
    // 17. out = xsum + hc2 @ fc2_w + fc2_b
    gemm_tc<<<dim3(3, ROWS/128), 256>>>(hc2, fc2_w, CFF, nullptr, nullptr, 0,
                                        fc2_b, nullptr, xsum, nullptr,
                                        out, ROWS, DIMC, DIMC, 0);
}

// round 4
// speedup vs baseline: 1.5976x; 1.3717x over previous
#include <cuda_runtime.h>
#include <cuda_bf16.h>
#include <math.h>

// ---------------------------------------------------------------------------
// Problem constants
// ---------------------------------------------------------------------------
#define BATCH 8
#define NTOK 4096
#define ROWS (BATCH*NTOK)
#define DIMC 180
#define HEADS 6
#define HD 30
#define QKVW 540
#define MTOK 64
#define RDIM 10
#define GS 128
#define NG 32
#define WS 16
#define WINN 256
#define NWIN 128
#define MLP_HID 360
#define DTD 64
#define CFF 424
#define HH 64
#define WW 64

// ---------------------------------------------------------------------------
// Scratch
// ---------------------------------------------------------------------------
__device__ float g_xn   [ROWS*DIMC];
__device__ float g_qkv  [ROWS*QKVW];
__device__ float g_qatd [ROWS*RDIM];
__device__ float g_kkn  [BATCH*MTOK*RDIM];
__device__ float g_vv   [BATCH*MTOK*DIMC];
__device__ float g_tdpr [BATCH*MTOK*DTD];
__device__ float g_patd [ROWS*MTOK];
__device__ int   g_tkid [ROWS];
__device__ int   g_sidx [ROWS];
__device__ int   g_cnt  [BATCH*MTOK];
__device__ int   g_off  [BATCH*MTOK];
__device__ float g_yaca [ROWS*DIMC];
__device__ float g_ywin [ROWS*DIMC];
__device__ float g_xsum [ROWS*DIMC];
__device__ float g_x2n  [ROWS*DIMC];
__device__ float g_hc   [ROWS*CFF];
__device__ float g_hc2  [ROWS*CFF];
__device__ float g_wbias[HEADS*WINN*WINN];

// ---------------------------------------------------------------------------
// Helpers
// ---------------------------------------------------------------------------
__device__ __forceinline__ float warp_sum(float v) {
    #pragma unroll
    for (int o = 16; o; o >>= 1) v += __shfl_xor_sync(0xffffffffu, v, o);
    return v;
}
__device__ __forceinline__ float gelu_exact(float v) {
    return 0.5f * v * (1.0f + erff(v * 0.70710678118654752440f));
}
__device__ __forceinline__ unsigned long long pack2(float lo, float hi) {
    unsigned long long r;
    asm("mov.b64 %0,{%1,%2};" : "=l"(r) : "f"(lo), "f"(hi));
    return r;
}
__device__ __forceinline__ void unpack2(unsigned long long v, float& lo, float& hi) {
    asm("mov.b64 {%0,%1},%2;" : "=f"(lo), "=f"(hi) : "l"(v));
}
__device__ __forceinline__ void fma2(unsigned long long& d, unsigned long long a,
                                     unsigned long long b) {
    asm("fma.rn.f32x2 %0,%1,%2,%0;" : "+l"(d) : "l"(a), "l"(b));
}
__device__ __forceinline__ unsigned long long mul2(unsigned long long a, unsigned long long b) {
    unsigned long long r;
    asm("mul.rn.f32x2 %0,%1,%2;" : "=l"(r) : "l"(a), "l"(b));
    return r;
}
__device__ __forceinline__ unsigned smem_u32(const void* p) {
    return (unsigned)__cvta_generic_to_shared(p);
}

// ---------------------------------------------------------------------------
// LayerNorm (+ optional fused 10-dim q projection): one warp per row.
// ---------------------------------------------------------------------------
__global__ void ln_kernel(const float* __restrict__ x, const float* __restrict__ g,
                          const float* __restrict__ b, float* __restrict__ out,
                          const float* __restrict__ wq, const float* __restrict__ bq,
                          float* __restrict__ qout) {
    __shared__ float ws[1920];
    __shared__ float bqs[16];
    int tid = threadIdx.x;
    if (wq) {
        for (int i = tid; i < 1920; i += 256) ws[i] = (i < DIMC * RDIM) ? wq[i] : 0.f;
        if (tid < RDIM) bqs[tid] = bq[tid];
        __syncthreads();
    }
    int row = (blockIdx.x * blockDim.x + tid) >> 5;
    if (row >= ROWS) return;
    int lane = tid & 31;
    const float* xr = x + (size_t)row * DIMC;
    float v[6], s = 0.f, s2 = 0.f;
    #pragma unroll
    for (int k = 0; k < 6; k++) {
        int c = lane + k * 32;
        v[k] = (c < DIMC) ? xr[c] : 0.f;
        s += v[k]; s2 += v[k] * v[k];
    }
    s = warp_sum(s); s2 = warp_sum(s2);
    float mu = s * (1.f / DIMC);
    float var = s2 * (1.f / DIMC) - mu * mu;
    float rstd = rsqrtf(var + 1e-5f);
    float nv[6];
    float* orow = out + (size_t)row * DIMC;
    #pragma unroll
    for (int k = 0; k < 6; k++) {
        int c = lane + k * 32;
        nv[k] = (c < DIMC) ? ((v[k] - mu) * rstd * g[c] + b[c]) : 0.f;
        if (c < DIMC) orow[c] = nv[k];
    }
    if (wq) {
        float myq = 0.f;
        #pragma unroll
        for (int o = 0; o < RDIM; o++) {
            float p = 0.f;
            #pragma unroll
            for (int k = 0; k < 6; k++) p += nv[k] * ws[(lane + 32 * k) * RDIM + o];
            p = warp_sum(p);
            if (lane == o) myq = p + bqs[o];
        }
        if (lane < RDIM) qout[(size_t)row * RDIM + lane] = myq;
    }
}

// ---------------------------------------------------------------------------
// Tensor-core tf32 GEMM with cp.async double-buffering; up to 3 fused passes.
// C = act( A1@W1 + A2@W2 + A3@W3(batched) + b1 + b2 + add1 )
// BM=128, BN=64, BK=16, 256 threads. Raw fp32 bits fed as tf32 (truncation).
// ---------------------------------------------------------------------------
struct GPass { const float* A; const float* W; int K; int kt; };

__global__ __launch_bounds__(256) void gemm_tc(
        const float* __restrict__ A1, const float* __restrict__ W1, int K1,
        const float* __restrict__ A2, const float* __restrict__ W2, int K2,
        const float* __restrict__ A3, const float* __restrict__ W3base, long w3_stride, int K3,
        const float* __restrict__ b1, const float* __restrict__ b2,
        const float* __restrict__ add1,
        float* __restrict__ C, int M, int N, int ldc, int act) {
    __shared__ float As[2][128][24];
    __shared__ float Ws[2][16][68];
    int tid  = threadIdx.x;
    int lane = tid & 31;
    int warp = tid >> 5;
    int warpM = warp & 3;
    int warpN = warp >> 2;
    int gId = lane >> 2;
    int tig = lane & 3;
    int row0 = blockIdx.y * 128;
    int col0 = blockIdx.x * 64;

    GPass ps[3];
    int np = 0;
    if (A1 && K1 > 0) ps[np++] = {A1, W1, K1, (K1 + 15) >> 4};
    if (A2 && K2 > 0) ps[np++] = {A2, W2, K2, (K2 + 15) >> 4};
    if (A3 && K3 > 0) ps[np++] = {A3, W3base + (size_t)(row0 >> 12) * w3_stride, K3, (K3 + 15) >> 4};
    int total = 0;
    for (int p = 0; p < np; p++) total += ps[p].kt;

    auto copy_tile = [&](int gi, int buf) {
        int p = 0, loc = gi;
        while (loc >= ps[p].kt) { loc -= ps[p].kt; p++; }
        const float* A = ps[p].A;
        const float* W = ps[p].W;
        int K = ps[p].K;
        int k0 = loc << 4;
        #pragma unroll
        for (int f = 0; f < 2; f++) {
            int cch = tid + f * 256;
            int m = cch >> 2, kk = (cch & 3) << 2;
            int gk = k0 + kk;
            int rem = K - gk;
            int bytes = (rem <= 0) ? 0 : ((rem >= 4) ? 16 : rem * 4);
            const float* src = bytes ? (A + (size_t)(row0 + m) * K + gk) : A;
            unsigned dst = smem_u32(&As[buf][m][kk]);
            asm volatile("cp.async.ca.shared.global [%0], [%1], 16, %2;"
                         :: "r"(dst), "l"(src), "r"(bytes));
        }
        {
            int kk = tid >> 4, n4 = (tid & 15) << 2;
            int gk = k0 + kk, gn = col0 + n4;
            int bytes = 0;
            if (gk < K) {
                int nb = N - gn;
                bytes = (nb <= 0) ? 0 : ((nb >= 4) ? 16 : nb * 4);
            }
            const float* src = bytes ? (W + (size_t)gk * N + gn) : W;
            unsigned dst = smem_u32(&Ws[buf][kk][n4]);
            asm volatile("cp.async.ca.shared.global [%0], [%1], 16, %2;"
                         :: "r"(dst), "l"(src), "r"(bytes));
        }
    };

    float d[2][4][4];
    #pragma unroll
    for (int mt = 0; mt < 2; mt++)
        #pragma unroll
        for (int nt = 0; nt < 4; nt++)
            #pragma unroll
            for (int i = 0; i < 4; i++) d[mt][nt][i] = 0.f;

    copy_tile(0, 0);
    asm volatile("cp.async.commit_group;");
    for (int i = 0; i < total; i++) {
        if (i + 1 < total) {
            copy_tile(i + 1, (i + 1) & 1);
            asm volatile("cp.async.commit_group;");
            asm volatile("cp.async.wait_group 1;");
        } else {
            asm volatile("cp.async.wait_group 0;");
        }
        __syncthreads();
        int buf = i & 1;
        #pragma unroll
        for (int ks = 0; ks < 2; ks++) {
            int kb = ks * 8;
            unsigned a[2][4], bfr[4][2];
            #pragma unroll
            for (int mt = 0; mt < 2; mt++) {
                int m0 = warpM * 32 + mt * 16;
                a[mt][0] = __float_as_uint(As[buf][m0 + gId    ][kb + tig    ]);
                a[mt][1] = __float_as_uint(As[buf][m0 + gId + 8][kb + tig    ]);
                a[mt][2] = __float_as_uint(As[buf][m0 + gId    ][kb + tig + 4]);
                a[mt][3] = __float_as_uint(As[buf][m0 + gId + 8][kb + tig + 4]);
            }
            #pragma unroll
            for (int nt = 0; nt < 4; nt++) {
                int n0 = warpN * 32 + nt * 8;
                bfr[nt][0] = __float_as_uint(Ws[buf][kb + tig    ][n0 + gId]);
                bfr[nt][1] = __float_as_uint(Ws[buf][kb + tig + 4][n0 + gId]);
            }
            #pragma unroll
            for (int mt = 0; mt < 2; mt++)
                #pragma unroll
                for (int nt = 0; nt < 4; nt++) {
                    asm volatile(
                        "mma.sync.aligned.m16n8k8.row.col.f32.tf32.tf32.f32 "
                        "{%0,%1,%2,%3},{%4,%5,%6,%7},{%8,%9},{%0,%1,%2,%3};"
                        : "+f"(d[mt][nt][0]), "+f"(d[mt][nt][1]),
                          "+f"(d[mt][nt][2]), "+f"(d[mt][nt][3])
                        : "r"(a[mt][0]), "r"(a[mt][1]), "r"(a[mt][2]), "r"(a[mt][3]),
                          "r"(bfr[nt][0]), "r"(bfr[nt][1]));
                }
        }
        __syncthreads();
    }

    #pragma unroll
    for (int mt = 0; mt < 2; mt++) {
        #pragma unroll
        for (int nt = 0; nt < 4; nt++) {
            #pragma unroll
            for (int i = 0; i < 4; i++) {
                int r = row0 + warpM * 32 + mt * 16 + gId + (i >> 1) * 8;
                int c = col0 + warpN * 32 + nt * 8 + tig * 2 + (i & 1);
                if (c < N) {
                    float v = d[mt][nt][i];
                    if (b1)   v += b1[c];
                    if (b2)   v += b2[c];
                    if (add1) v += add1[(size_t)r * N + c];
                    if (act)  v = gelu_exact(v);
                    C[(size_t)r * ldc + c] = v;
                }
            }
        }
    }
}

// ---------------------------------------------------------------------------
// Small GEMM for dictionary projections (512 rows)
// ---------------------------------------------------------------------------
__global__ void smallmm_kernel(const float* __restrict__ A, const float* __restrict__ W,
                               const float* __restrict__ bias, float* __restrict__ C,
                               int N, int K) {
    int r = blockIdx.x;
    __shared__ float as[192];
    const float* ar = A + (size_t)r * K;
    for (int k = threadIdx.x; k < K; k += blockDim.x) as[k] = ar[k];
    __syncthreads();
    for (int c = threadIdx.x; c < N; c += blockDim.x) {
        float acc = bias ? bias[c] : 0.f;
        for (int k = 0; k < K; k++) acc += as[k] * W[(size_t)k * N + c];
        C[(size_t)r * N + c] = acc;
    }
}

__global__ void l2norm10_kernel(float* __restrict__ d, int rows) {
    int r = (blockIdx.x * blockDim.x + threadIdx.x) >> 5;
    if (r >= rows) return;
    int lane = threadIdx.x & 31;
    float v = (lane < RDIM) ? d[(size_t)r * RDIM + lane] : 0.f;
    float ss = warp_sum(v * v);
    float inv = 1.f / fmaxf(sqrtf(ss), 1e-12f);
    if (lane < RDIM) d[(size_t)r * RDIM + lane] = v * inv;
}

// ---------------------------------------------------------------------------
// ATD: softmax probs P[ROWS][64] + argmax tkid. One warp per token.
// ---------------------------------------------------------------------------
__global__ void atd_kernel(const float* __restrict__ qatd, const float* __restrict__ kkn,
                           const float* __restrict__ scale,
                           float* __restrict__ P, int* __restrict__ tkid) {
    int t = (blockIdx.x * blockDim.x + threadIdx.x) >> 5;
    int lane = threadIdx.x & 31;
    if (t >= ROWS) return;
    int b = t >> 12;
    float q = (lane < RDIM) ? qatd[(size_t)t * RDIM + lane] : 0.f;
    float ss = warp_sum(q * q);
    float qn = q * (1.f / fmaxf(sqrtf(ss), 1e-12f));
    const float* kb = kkn + (size_t)b * MTOK * RDIM;
    float s0 = 0.f, s1 = 0.f;
    #pragma unroll
    for (int d = 0; d < RDIM; d++) {
        float qd = __shfl_sync(0xffffffffu, qn, d);
        s0 += qd * kb[lane * RDIM + d];
        s1 += qd * kb[(lane + 32) * RDIM + d];
    }
    float sc = fminf(fmaxf(scale[0], 0.f), 3.f);
    float ls = 1.f + sc * 4.15888308335967186f;  // log(64)
    s0 *= ls; s1 *= ls;
    float mv = fmaxf(s0, s1);
    int mi = (s0 >= s1) ? lane : lane + 32;
    #pragma unroll
    for (int o = 16; o; o >>= 1) {
        float ov = __shfl_xor_sync(0xffffffffu, mv, o);
        int   oi = __shfl_xor_sync(0xffffffffu, mi, o);
        if (ov > mv || (ov == mv && oi < mi)) { mv = ov; mi = oi; }
    }
    float p0 = __expf(s0 - mv), p1 = __expf(s1 - mv);
    float sum = warp_sum(p0 + p1);
    float inv = 1.f / sum;
    P[(size_t)t * MTOK + lane]      = p0 * inv;
    P[(size_t)t * MTOK + lane + 32] = p1 * inv;
    if (lane == 0) tkid[t] = mi;
}

// ---------------------------------------------------------------------------
// Stable counting sort of tk_id per batch
// ---------------------------------------------------------------------------
__global__ void zero_cnt_kernel() {
    if (threadIdx.x < BATCH * MTOK) g_cnt[threadIdx.x] = 0;
}
__global__ void hist_kernel(const int* __restrict__ tkid) {
    int i = blockIdx.x * blockDim.x + threadIdx.x;
    if (i < ROWS) atomicAdd(&g_cnt[(i >> 12) * MTOK + tkid[i]], 1);
}
__global__ void offs_kernel() {
    int b = threadIdx.x;
    if (b < BATCH) {
        int r = 0;
        for (int j = 0; j < MTOK; j++) { g_off[b * MTOK + j] = r; r += g_cnt[b * MTOK + j]; }
    }
}
__global__ void scatter_kernel(const int* __restrict__ tkid, int* __restrict__ sidx) {
    int b = blockIdx.x >> 6, bin = blockIdx.x & 63;
    const int* tk = tkid + b * NTOK;
    __shared__ int sc[256];
    int t = threadIdx.x;
    int start = t * 16;
    int cnt = 0;
    #pragma unroll
    for (int k = 0; k < 16; k++) cnt += (tk[start + k] == bin);
    sc[t] = cnt;
    __syncthreads();
    for (int d = 1; d < 256; d <<= 1) {
        int v = (t >= d) ? sc[t - d] : 0;
        __syncthreads();
        sc[t] += v;
        __syncthreads();
    }
    int pos = g_off[b * MTOK + bin] + sc[t] - cnt;
    for (int k = 0; k < 16; k++)
        if (tk[start + k] == bin) sidx[b * NTOK + pos++] = start + k;
}

// ---------------------------------------------------------------------------
// AC_MSA grouped attention (f32x2 math, full 32-float rows)
// ---------------------------------------------------------------------------
__global__ void acmsa_kernel(const float* __restrict__ qkv, const int* __restrict__ sidx,
                             float* __restrict__ yout) {
    int bi = blockIdx.x;
    int hh = bi % HEADS;
    int g  = (bi / HEADS) % NG;
    int b  = bi / (HEADS * NG);
    int t = threadIdx.x;
    __shared__ __align__(16) float Ks[GS][32], Vs[GS][32];
    int rn = sidx[b * NTOK + g * GS + t];
    const float* base = qkv + ((size_t)(b * NTOK + rn)) * QKVW + hh * HD;
    const float scale = 0.18257418583505536f;   // 30^-0.5
    float q[32];
    #pragma unroll
    for (int d = 0; d < HD; d++) {
        q[d] = base[d] * scale;
        Ks[t][d] = base[180 + d];
        Vs[t][d] = base[360 + d];
    }
    q[30] = q[31] = 0.f;
    Ks[t][30] = Ks[t][31] = 0.f;
    Vs[t][30] = Vs[t][31] = 0.f;
    unsigned long long q2[16];
    #pragma unroll
    for (int i = 0; i < 16; i++) q2[i] = pack2(q[2*i], q[2*i+1]);
    __syncthreads();
    float m = -1e30f, l = 0.f;
    unsigned long long acc2[16];
    #pragma unroll
    for (int i = 0; i < 16; i++) acc2[i] = pack2(0.f, 0.f);
    for (int j = 0; j < GS; j++) {
        const unsigned long long* k2 = (const unsigned long long*)Ks[j];
        unsigned long long s2 = pack2(0.f, 0.f);
        #pragma unroll
        for (int i = 0; i < 16; i++) fma2(s2, q2[i], k2[i]);
        float slo, shi; unpack2(s2, slo, shi);
        float s = slo + shi;
        float mn = fmaxf(m, s);
        float co = __expf(m - mn);
        float p  = __expf(s - mn);
        l = l * co + p; m = mn;
        unsigned long long co2 = pack2(co, co), p2 = pack2(p, p);
        const unsigned long long* v2 = (const unsigned long long*)Vs[j];
        #pragma unroll
        for (int i = 0; i < 16; i++) {
            unsigned long long t0 = mul2(v2[i], p2);
            asm("fma.rn.f32x2 %0,%0,%1,%2;" : "+l"(acc2[i]) : "l"(co2), "l"(t0));
        }
    }
    float inv = 1.f / l;
    float* orow = yout + ((size_t)(b * NTOK + rn)) * DIMC + hh * HD;
    #pragma unroll
    for (int i = 0; i < 15; i++) {
        float lo, hi; unpack2(acc2[i], lo, hi);
        orow[2*i] = lo * inv;
        orow[2*i+1] = hi * inv;
    }
}

// ---------------------------------------------------------------------------
// Window attention bias expansion
// ---------------------------------------------------------------------------
__global__ void wbias_kernel(const int* __restrict__ rpi, const float* __restrict__ rpb) {
    int e = blockIdx.x * blockDim.x + threadIdx.x;
    if (e < WINN * WINN) {
        int idx = rpi[e];
        #pragma unroll
        for (int h = 0; h < HEADS; h++) g_wbias[h * WINN * WINN + e] = rpb[idx * HEADS + h];
    }
}

// ---------------------------------------------------------------------------
// Window attention (f32x2 math, full 32-float rows)
// ---------------------------------------------------------------------------
__global__ void winattn_kernel(const float* __restrict__ qkv, float* __restrict__ yout) {
    extern __shared__ float sm[];
    float* Ks = sm;
    float* Vs = sm + WINN * 32;
    int bi = blockIdx.x;
    int hh = bi % HEADS;
    int wdx = bi / HEADS;
    int b = wdx >> 4;
    int wy = (wdx >> 2) & 3;
    int wx = wdx & 3;
    int t = threadIdx.x;
    int iy = t >> 4, ix = t & 15;
    int nidx = (wy * WS + iy) * WW + (wx * WS + ix);
    size_t rowbase = ((size_t)(b * NTOK + nidx)) * QKVW + hh * HD;
    const float scale = 0.18257418583505536f;
    float q[32];
    #pragma unroll
    for (int d = 0; d < HD; d++) {
        q[d] = qkv[rowbase + d] * scale;
        Ks[t * 32 + d] = qkv[rowbase + 180 + d];
        Vs[t * 32 + d] = qkv[rowbase + 360 + d];
    }
    q[30] = q[31] = 0.f;
    Ks[t * 32 + 30] = Ks[t * 32 + 31] = 0.f;
    Vs[t * 32 + 30] = Vs[t * 32 + 31] = 0.f;
    unsigned long long q2[16];
    #pragma unroll
    for (int i = 0; i < 16; i++) q2[i] = pack2(q[2*i], q[2*i+1]);
    __syncthreads();
    const float* brow = g_wbias + ((size_t)hh * WINN + t) * WINN;
    float m = -1e30f, l = 0.f;
    unsigned long long acc2[16];
    #pragma unroll
    for (int i = 0; i < 16; i++) acc2[i] = pack2(0.f, 0.f);
    for (int j = 0; j < WINN; j++) {
        const unsigned long long* k2 = (const unsigned long long*)(Ks + j * 32);
        unsigned long long s2 = pack2(0.f, 0.f);
        #pragma unroll
        for (int i = 0; i < 16; i++) fma2(s2, q2[i], k2[i]);
        float slo, shi; unpack2(s2, slo, shi);
        float s = slo + shi + brow[j];
        float mn = fmaxf(m, s);
        float co = __expf(m - mn);
        float p  = __expf(s - mn);
        l = l * co + p; m = mn;
        unsigned long long co2 = pack2(co, co), p2 = pack2(p, p);
        const unsigned long long* v2 = (const unsigned long long*)(Vs + j * 32);
        #pragma unroll
        for (int i = 0; i < 16; i++) {
            unsigned long long t0 = mul2(v2[i], p2);
            asm("fma.rn.f32x2 %0,%0,%1,%2;" : "+l"(acc2[i]) : "l"(co2), "l"(t0));
        }
    }
    float inv = 1.f / l;
    float* orow = yout + ((size_t)(b * NTOK + nidx)) * DIMC + hh * HD;
    #pragma unroll
    for (int i = 0; i < 15; i++) {
        float lo, hi; unpack2(acc2[i], lo, hi);
        orow[2*i] = lo * inv;
        orow[2*i+1] = hi * inv;
    }
}

// ---------------------------------------------------------------------------
// Gather per-token dictionary features into hc[:, 360:424]
// ---------------------------------------------------------------------------
__global__ void gathertd_kernel(const float* __restrict__ tdproj, const int* __restrict__ tkid,
                                float* __restrict__ hc) {
    int e = blockIdx.x * blockDim.x + threadIdx.x;
    if (e < ROWS * DTD) {
        int r = e >> 6, j = e & 63;
        int b = r >> 12;
        hc[(size_t)r * CFF + MLP_HID + j] = tdproj[((size_t)b * MTOK + tkid[r]) * DTD + j];
    }
}

// ---------------------------------------------------------------------------
// Depthwise 5x5 conv, tiled: 16x16 pixels x 8 channels per block.
// ---------------------------------------------------------------------------
#define DWCH 8
__global__ void dwconv_kernel(const float* __restrict__ hc, const float* __restrict__ w,
                              const float* __restrict__ bias, float* __restrict__ hc2) {
    __shared__ float smd[20 * 20 * DWCH];
    __shared__ float wsm[25][DWCH];
    __shared__ float bsm[DWCH];
    int tid = threadIdx.x;
    int c0 = blockIdx.y * DWCH;
    int b  = blockIdx.z;
    int tileY = (blockIdx.x >> 2) * 16, tileX = (blockIdx.x & 3) * 16;
    if (tid < 200) { int t5 = tid % 25, j = tid / 25; wsm[t5][j] = w[(c0 + j) * 25 + t5]; }
    if (tid < DWCH) bsm[tid] = bias[c0 + tid];
    for (int i = tid; i < 800; i += 256) {
        int cell = i >> 1, half = i & 1;
        int cy = cell / 20, cx = cell % 20;
        int gy = tileY + cy - 2, gx = tileX + cx - 2;
        float4 v = {0.f, 0.f, 0.f, 0.f};
        if (gy >= 0 && gy < 64 && gx >= 0 && gx < 64)
            v = *(const float4*)&hc[(((size_t)b << 12) + (gy << 6) + gx) * CFF + c0 + half * 4];
        *(float4*)&smd[cell * 8 + half * 4] = v;
    }
    __syncthreads();
    int ty = tid >> 4, tx = tid & 15;
    float acc[DWCH];
    #pragma unroll
    for (int j = 0; j < DWCH; j++) acc[j] = 0.f;
    #pragma unroll
    for (int ky = 0; ky < 5; ky++) {
        #pragma unroll
        for (int kx = 0; kx < 5; kx++) {
            const float* cp = &smd[((ty + ky) * 20 + tx + kx) * 8];
            float4 a0 = *(const float4*)cp;
            float4 a1 = *(const float4*)(cp + 4);
            int t5 = ky * 5 + kx;
            acc[0] += a0.x * wsm[t5][0];
            acc[1] += a0.y * wsm[t5][1];
            acc[2] += a0.z * wsm[t5][2];
            acc[3] += a0.w * wsm[t5][3];
            acc[4] += a1.x * wsm[t5][4];
            acc[5] += a1.y * wsm[t5][5];
            acc[6] += a1.z * wsm[t5][6];
            acc[7] += a1.w * wsm[t5][7];
        }
    }
    const float* ctr = &smd[((ty + 2) * 20 + tx + 2) * 8];
    size_t idx = (((size_t)b << 12) + ((size_t)(tileY + ty) << 6) + (tileX + tx)) * CFF + c0;
    float4 o0, o1;
    o0.x = ctr[0] + gelu_exact(acc[0] + bsm[0]);
    o0.y = ctr[1] + gelu_exact(acc[1] + bsm[1]);
    o0.z = ctr[2] + gelu_exact(acc[2] + bsm[2]);
    o0.w = ctr[3] + gelu_exact(acc[3] + bsm[3]);
    o1.x = ctr[4] + gelu_exact(acc[4] + bsm[4]);
    o1.y = ctr[5] + gelu_exact(acc[5] + bsm[5]);
    o1.z = ctr[6] + gelu_exact(acc[6] + bsm[6]);
    o1.w = ctr[7] + gelu_exact(acc[7] + bsm[7]);
    *(float4*)&hc2[idx] = o0;
    *(float4*)&hc2[idx + 4] = o1;
}

// ---------------------------------------------------------------------------
// Launch
// ---------------------------------------------------------------------------
extern "C" void kernel_launch(void* const* d_in, const int* in_sizes, int n_in,
                              void* d_out, int out_size) {
    const float* x        = (const float*)d_in[0];
    const float* td       = (const float*)d_in[1];
    const float* n1g      = (const float*)d_in[2];
    const float* n1b      = (const float*)d_in[3];
    const float* wqkv_w   = (const float*)d_in[4];
    const float* wqkv_b   = (const float*)d_in[5];
    const float* atd_wq_w = (const float*)d_in[6];
    const float* atd_wq_b = (const float*)d_in[7];
    const float* atd_wk_w = (const float*)d_in[8];
    const float* atd_wk_b = (const float*)d_in[9];
    const float* atd_wv_w = (const float*)d_in[10];
    const float* atd_wv_b = (const float*)d_in[11];
    const float* atd_sc   = (const float*)d_in[12];
    const float* aca_w    = (const float*)d_in[13];
    const float* aca_b    = (const float*)d_in[14];
    const float* win_rpb  = (const float*)d_in[15];
    const float* win_w    = (const float*)d_in[16];
    const float* win_b    = (const float*)d_in[17];
    const float* fctd_w   = (const float*)d_in[18];
    const float* fctd_b   = (const float*)d_in[19];
    const float* fc1_w    = (const float*)d_in[20];
    const float* fc1_b    = (const float*)d_in[21];
    const float* dw_w     = (const float*)d_in[22];
    const float* dw_b     = (const float*)d_in[23];
    const float* fc2_w    = (const float*)d_in[24];
    const float* fc2_b    = (const float*)d_in[25];
    const float* n2g      = (const float*)d_in[26];
    const float* n2b      = (const float*)d_in[27];
    const int*   rpi      = (const int*)d_in[28];
    float* out = (float*)d_out;

    float *xn, *qkv, *qatd, *kkn, *vv, *tdpr, *patd, *yaca, *ywin, *xsum, *x2n, *hc, *hc2;
    int *tkid, *sidx;
    cudaGetSymbolAddress((void**)&xn,   g_xn);
    cudaGetSymbolAddress((void**)&qkv,  g_qkv);
    cudaGetSymbolAddress((void**)&qatd, g_qatd);
    cudaGetSymbolAddress((void**)&kkn,  g_kkn);
    cudaGetSymbolAddress((void**)&vv,   g_vv);
    cudaGetSymbolAddress((void**)&tdpr, g_tdpr);
    cudaGetSymbolAddress((void**)&patd, g_patd);
    cudaGetSymbolAddress((void**)&yaca, g_yaca);
    cudaGetSymbolAddress((void**)&ywin, g_ywin);
    cudaGetSymbolAddress((void**)&xsum, g_xsum);
    cudaGetSymbolAddress((void**)&x2n,  g_x2n);
    cudaGetSymbolAddress((void**)&hc,   g_hc);
    cudaGetSymbolAddress((void**)&hc2,  g_hc2);
    cudaGetSymbolAddress((void**)&tkid, g_tkid);
    cudaGetSymbolAddress((void**)&sidx, g_sidx);

    // 1. LN1 (+ fused q_atd projection)
    ln_kernel<<<ROWS/8, 256>>>(x, n1g, n1b, xn, atd_wq_w, atd_wq_b, qatd);
    // 2. qkv = xn @ wqkv + b
    gemm_tc<<<dim3(9, ROWS/128), 256>>>(xn, wqkv_w, DIMC, nullptr, nullptr, 0,
                                        nullptr, nullptr, 0, 0,
                                        wqkv_b, nullptr, nullptr,
                                        qkv, ROWS, QKVW, QKVW, 0);
    // 3. dictionary projections
    smallmm_kernel<<<BATCH*MTOK, 32>>>(td, atd_wk_w, atd_wk_b, kkn, RDIM, DIMC);
    l2norm10_kernel<<<(BATCH*MTOK + 7)/8, 256>>>(kkn, BATCH*MTOK);
    smallmm_kernel<<<BATCH*MTOK, 192>>>(td, atd_wv_w, atd_wv_b, vv, DIMC, DIMC);
    smallmm_kernel<<<BATCH*MTOK, 64>>>(td, fctd_w, fctd_b, tdpr, DTD, DIMC);
    // 4. ATD probs + tk_id
    atd_kernel<<<ROWS/8, 256>>>(qatd, kkn, atd_sc, patd, tkid);
    // 5. stable counting sort
    zero_cnt_kernel<<<1, 512>>>();
    hist_kernel<<<ROWS/256, 256>>>(tkid);
    offs_kernel<<<1, 8>>>();
    scatter_kernel<<<BATCH*MTOK, 256>>>(tkid, sidx);
    // 6. grouped attention
    acmsa_kernel<<<BATCH*NG*HEADS, 128>>>(qkv, sidx, yaca);
    // 7. window attention
    wbias_kernel<<<WINN*WINN/256, 256>>>(rpi, win_rpb);
    cudaFuncSetAttribute(winattn_kernel, cudaFuncAttributeMaxDynamicSharedMemorySize, 65536);
    winattn_kernel<<<NWIN*HEADS, 256, 65536>>>(qkv, ywin);
    // 8. xsum = x + P@vv (batched) + yaca@aca_w + ywin@win_w + biases
    gemm_tc<<<dim3(3, ROWS/128), 256>>>(yaca, aca_w, DIMC, ywin, win_w, DIMC,
                                        patd, vv, (long)MTOK*DIMC, MTOK,
                                        aca_b, win_b, x,
                                        xsum, ROWS, DIMC, DIMC, 0);
    // 9. LN2
    ln_kernel<<<ROWS/8, 256>>>(xsum, n2g, n2b, x2n, nullptr, nullptr, nullptr);
    // 10. fc1 + GELU into hc[:, 0:360]
    gemm_tc<<<dim3(6, ROWS/128), 256>>>(x2n, fc1_w, DIMC, nullptr, nullptr, 0,
                                        nullptr, nullptr, 0, 0,
                                        fc1_b, nullptr, nullptr,
                                        hc, ROWS, MLP_HID, CFF, 1);
    // 11. gather td features into hc[:, 360:424]
    gathertd_kernel<<<ROWS*DTD/256, 256>>>(tdpr, tkid, hc);
    // 12. depthwise conv + gelu + residual (tiled)
    dwconv_kernel<<<dim3(16, CFF/DWCH, BATCH), 256>>>(hc, dw_w, dw_b, hc2);
    // 13. out = xsum + hc2 @ fc2_w + fc2_b
    gemm_tc<<<dim3(3, ROWS/128), 256>>>(hc2, fc2_w, CFF, nullptr, nullptr, 0,
                                        nullptr, nullptr, 0, 0,
                                        fc2_b, nullptr, xsum,
                                        out, ROWS, DIMC, DIMC, 0);
}

// round 5
// speedup vs baseline: 1.6806x; 1.0520x over previous
#include <cuda_runtime.h>
#include <cuda_bf16.h>
#include <math.h>

// ---------------------------------------------------------------------------
// Problem constants
// ---------------------------------------------------------------------------
#define BATCH 8
#define NTOK 4096
#define ROWS (BATCH*NTOK)
#define DIMC 180
#define HEADS 6
#define HD 30
#define QKVW 540
#define MTOK 64
#define RDIM 10
#define GS 128
#define NG 32
#define WS 16
#define WINN 256
#define NWIN 128
#define MLP_HID 360
#define DTD 64
#define CFF 424
#define HH 64
#define WW 64

// ---------------------------------------------------------------------------
// Scratch
// ---------------------------------------------------------------------------
__device__ float g_xn   [ROWS*DIMC];
__device__ float g_qkv  [ROWS*QKVW];
__device__ float g_qatd [ROWS*RDIM];
__device__ float g_kkn  [BATCH*MTOK*RDIM];
__device__ float g_vv   [BATCH*MTOK*DIMC];
__device__ float g_tdpr [BATCH*MTOK*DTD];
__device__ float g_patd [ROWS*MTOK];
__device__ int   g_tkid [ROWS];
__device__ int   g_sidx [ROWS];
__device__ float g_yaca [ROWS*DIMC];
__device__ float g_ywin [ROWS*DIMC];
__device__ float g_xsum [ROWS*DIMC];
__device__ float g_x2n  [ROWS*DIMC];
__device__ float g_hc   [ROWS*CFF];
__device__ float g_hc2  [ROWS*CFF];
__device__ float g_wbias[HEADS*WINN*WINN];

// ---------------------------------------------------------------------------
// Helpers
// ---------------------------------------------------------------------------
__device__ __forceinline__ float warp_sum(float v) {
    #pragma unroll
    for (int o = 16; o; o >>= 1) v += __shfl_xor_sync(0xffffffffu, v, o);
    return v;
}
__device__ __forceinline__ float gelu_exact(float v) {
    return 0.5f * v * (1.0f + erff(v * 0.70710678118654752440f));
}
__device__ __forceinline__ unsigned long long pack2(float lo, float hi) {
    unsigned long long r;
    asm("mov.b64 %0,{%1,%2};" : "=l"(r) : "f"(lo), "f"(hi));
    return r;
}
__device__ __forceinline__ void unpack2(unsigned long long v, float& lo, float& hi) {
    asm("mov.b64 {%0,%1},%2;" : "=f"(lo), "=f"(hi) : "l"(v));
}
__device__ __forceinline__ void fma2(unsigned long long& d, unsigned long long a,
                                     unsigned long long b) {
    asm("fma.rn.f32x2 %0,%1,%2,%0;" : "+l"(d) : "l"(a), "l"(b));
}
__device__ __forceinline__ unsigned long long mul2(unsigned long long a, unsigned long long b) {
    unsigned long long r;
    asm("mul.rn.f32x2 %0,%1,%2;" : "=l"(r) : "l"(a), "l"(b));
    return r;
}
__device__ __forceinline__ unsigned smem_u32(const void* p) {
    return (unsigned)__cvta_generic_to_shared(p);
}

// ---------------------------------------------------------------------------
// Fused dictionary projections: per td row -> vv(180), tdpr(64), kkn(10, l2n)
// ---------------------------------------------------------------------------
__global__ void dict_kernel(const float* __restrict__ td,
                            const float* __restrict__ wk_w, const float* __restrict__ wk_b,
                            const float* __restrict__ wv_w, const float* __restrict__ wv_b,
                            const float* __restrict__ ftd_w, const float* __restrict__ ftd_b,
                            float* __restrict__ kkn, float* __restrict__ vv,
                            float* __restrict__ tdpr) {
    int r = blockIdx.x;                 // 0..511
    __shared__ float as[DIMC];
    __shared__ float kbuf[RDIM];
    int tid = threadIdx.x;
    const float* ar = td + (size_t)r * DIMC;
    if (tid < DIMC) as[tid] = ar[tid];
    __syncthreads();
    if (tid < DIMC) {
        float acc = wv_b[tid];
        #pragma unroll 4
        for (int k = 0; k < DIMC; k++) acc += as[k] * wv_w[(size_t)k * DIMC + tid];
        vv[(size_t)r * DIMC + tid] = acc;
    } else if (tid < DIMC + DTD) {
        int c = tid - DIMC;
        float acc = ftd_b[c];
        #pragma unroll 4
        for (int k = 0; k < DIMC; k++) acc += as[k] * ftd_w[(size_t)k * DTD + c];
        tdpr[(size_t)r * DTD + c] = acc;
    } else if (tid < DIMC + DTD + RDIM) {
        int c = tid - DIMC - DTD;
        float acc = wk_b[c];
        #pragma unroll 4
        for (int k = 0; k < DIMC; k++) acc += as[k] * wk_w[(size_t)k * RDIM + c];
        kbuf[c] = acc;
    }
    __syncthreads();
    if (tid >= DIMC + DTD && tid < DIMC + DTD + RDIM) {
        int c = tid - DIMC - DTD;
        float ss = 0.f;
        #pragma unroll
        for (int j = 0; j < RDIM; j++) ss += kbuf[j] * kbuf[j];
        float inv = 1.f / fmaxf(sqrtf(ss), 1e-12f);
        kkn[(size_t)r * RDIM + c] = kbuf[c] * inv;
    }
}

// ---------------------------------------------------------------------------
// Window attention bias expansion
// ---------------------------------------------------------------------------
__global__ void wbias_kernel(const int* __restrict__ rpi, const float* __restrict__ rpb) {
    int e = blockIdx.x * blockDim.x + threadIdx.x;
    if (e < WINN * WINN) {
        int idx = rpi[e];
        #pragma unroll
        for (int h = 0; h < HEADS; h++) g_wbias[h * WINN * WINN + e] = rpb[idx * HEADS + h];
    }
}

// ---------------------------------------------------------------------------
// LayerNorm (+ optional fused 10-dim q projection): one warp per row.
// ---------------------------------------------------------------------------
__global__ void ln_kernel(const float* __restrict__ x, const float* __restrict__ g,
                          const float* __restrict__ b, float* __restrict__ out,
                          const float* __restrict__ wq, const float* __restrict__ bq,
                          float* __restrict__ qout) {
    __shared__ float ws[1920];
    __shared__ float bqs[16];
    int tid = threadIdx.x;
    if (wq) {
        for (int i = tid; i < 1920; i += 256) ws[i] = (i < DIMC * RDIM) ? wq[i] : 0.f;
        if (tid < RDIM) bqs[tid] = bq[tid];
        __syncthreads();
    }
    int row = (blockIdx.x * blockDim.x + tid) >> 5;
    if (row >= ROWS) return;
    int lane = tid & 31;
    const float* xr = x + (size_t)row * DIMC;
    float v[6], s = 0.f, s2 = 0.f;
    #pragma unroll
    for (int k = 0; k < 6; k++) {
        int c = lane + k * 32;
        v[k] = (c < DIMC) ? xr[c] : 0.f;
        s += v[k]; s2 += v[k] * v[k];
    }
    s = warp_sum(s); s2 = warp_sum(s2);
    float mu = s * (1.f / DIMC);
    float var = s2 * (1.f / DIMC) - mu * mu;
    float rstd = rsqrtf(var + 1e-5f);
    float nv[6];
    float* orow = out + (size_t)row * DIMC;
    #pragma unroll
    for (int k = 0; k < 6; k++) {
        int c = lane + k * 32;
        nv[k] = (c < DIMC) ? ((v[k] - mu) * rstd * g[c] + b[c]) : 0.f;
        if (c < DIMC) orow[c] = nv[k];
    }
    if (wq) {
        float myq = 0.f;
        #pragma unroll
        for (int o = 0; o < RDIM; o++) {
            float p = 0.f;
            #pragma unroll
            for (int k = 0; k < 6; k++) p += nv[k] * ws[(lane + 32 * k) * RDIM + o];
            p = warp_sum(p);
            if (lane == o) myq = p + bqs[o];
        }
        if (lane < RDIM) qout[(size_t)row * RDIM + lane] = myq;
    }
}

// ---------------------------------------------------------------------------
// Tensor-core tf32 GEMM with cp.async double-buffering; up to 3 fused passes.
// BM=128, BN=64, BK=16, 256 threads. As padded to 28 (16B-aligned, no 2-way
// bank conflict on fragment loads).
// ---------------------------------------------------------------------------
struct GPass { const float* A; const float* W; int K; int kt; };

__global__ __launch_bounds__(256) void gemm_tc(
        const float* __restrict__ A1, const float* __restrict__ W1, int K1,
        const float* __restrict__ A2, const float* __restrict__ W2, int K2,
        const float* __restrict__ A3, const float* __restrict__ W3base, long w3_stride, int K3,
        const float* __restrict__ b1, const float* __restrict__ b2,
        const float* __restrict__ add1,
        float* __restrict__ C, int M, int N, int ldc, int act) {
    __shared__ float As[2][128][28];
    __shared__ float Ws[2][16][68];
    int tid  = threadIdx.x;
    int lane = tid & 31;
    int warp = tid >> 5;
    int warpM = warp & 3;
    int warpN = warp >> 2;
    int gId = lane >> 2;
    int tig = lane & 3;
    int row0 = blockIdx.y * 128;
    int col0 = blockIdx.x * 64;

    GPass ps[3];
    int np = 0;
    if (A1 && K1 > 0) ps[np++] = {A1, W1, K1, (K1 + 15) >> 4};
    if (A2 && K2 > 0) ps[np++] = {A2, W2, K2, (K2 + 15) >> 4};
    if (A3 && K3 > 0) ps[np++] = {A3, W3base + (size_t)(row0 >> 12) * w3_stride, K3, (K3 + 15) >> 4};
    int total = 0;
    for (int p = 0; p < np; p++) total += ps[p].kt;

    auto copy_tile = [&](int gi, int buf) {
        int p = 0, loc = gi;
        while (loc >= ps[p].kt) { loc -= ps[p].kt; p++; }
        const float* A = ps[p].A;
        const float* W = ps[p].W;
        int K = ps[p].K;
        int k0 = loc << 4;
        #pragma unroll
        for (int f = 0; f < 2; f++) {
            int cch = tid + f * 256;
            int m = cch >> 2, kk = (cch & 3) << 2;
            int gk = k0 + kk;
            int rem = K - gk;
            int bytes = (rem <= 0) ? 0 : ((rem >= 4) ? 16 : rem * 4);
            const float* src = bytes ? (A + (size_t)(row0 + m) * K + gk) : A;
            unsigned dst = smem_u32(&As[buf][m][kk]);
            asm volatile("cp.async.ca.shared.global [%0], [%1], 16, %2;"
                         :: "r"(dst), "l"(src), "r"(bytes));
        }
        {
            int kk = tid >> 4, n4 = (tid & 15) << 2;
            int gk = k0 + kk, gn = col0 + n4;
            int bytes = 0;
            if (gk < K) {
                int nb = N - gn;
                bytes = (nb <= 0) ? 0 : ((nb >= 4) ? 16 : nb * 4);
            }
            const float* src = bytes ? (W + (size_t)gk * N + gn) : W;
            unsigned dst = smem_u32(&Ws[buf][kk][n4]);
            asm volatile("cp.async.ca.shared.global [%0], [%1], 16, %2;"
                         :: "r"(dst), "l"(src), "r"(bytes));
        }
    };

    float d[2][4][4];
    #pragma unroll
    for (int mt = 0; mt < 2; mt++)
        #pragma unroll
        for (int nt = 0; nt < 4; nt++)
            #pragma unroll
            for (int i = 0; i < 4; i++) d[mt][nt][i] = 0.f;

    copy_tile(0, 0);
    asm volatile("cp.async.commit_group;");
    for (int i = 0; i < total; i++) {
        if (i + 1 < total) {
            copy_tile(i + 1, (i + 1) & 1);
            asm volatile("cp.async.commit_group;");
            asm volatile("cp.async.wait_group 1;");
        } else {
            asm volatile("cp.async.wait_group 0;");
        }
        __syncthreads();
        int buf = i & 1;
        #pragma unroll
        for (int ks = 0; ks < 2; ks++) {
            int kb = ks * 8;
            unsigned a[2][4], bfr[4][2];
            #pragma unroll
            for (int mt = 0; mt < 2; mt++) {
                int m0 = warpM * 32 + mt * 16;
                a[mt][0] = __float_as_uint(As[buf][m0 + gId    ][kb + tig    ]);
                a[mt][1] = __float_as_uint(As[buf][m0 + gId + 8][kb + tig    ]);
                a[mt][2] = __float_as_uint(As[buf][m0 + gId    ][kb + tig + 4]);
                a[mt][3] = __float_as_uint(As[buf][m0 + gId + 8][kb + tig + 4]);
            }
            #pragma unroll
            for (int nt = 0; nt < 4; nt++) {
                int n0 = warpN * 32 + nt * 8;
                bfr[nt][0] = __float_as_uint(Ws[buf][kb + tig    ][n0 + gId]);
                bfr[nt][1] = __float_as_uint(Ws[buf][kb + tig + 4][n0 + gId]);
            }
            #pragma unroll
            for (int mt = 0; mt < 2; mt++)
                #pragma unroll
                for (int nt = 0; nt < 4; nt++) {
                    asm volatile(
                        "mma.sync.aligned.m16n8k8.row.col.f32.tf32.tf32.f32 "
                        "{%0,%1,%2,%3},{%4,%5,%6,%7},{%8,%9},{%0,%1,%2,%3};"
                        : "+f"(d[mt][nt][0]), "+f"(d[mt][nt][1]),
                          "+f"(d[mt][nt][2]), "+f"(d[mt][nt][3])
                        : "r"(a[mt][0]), "r"(a[mt][1]), "r"(a[mt][2]), "r"(a[mt][3]),
                          "r"(bfr[nt][0]), "r"(bfr[nt][1]));
                }
        }
        __syncthreads();
    }

    #pragma unroll
    for (int mt = 0; mt < 2; mt++) {
        #pragma unroll
        for (int nt = 0; nt < 4; nt++) {
            #pragma unroll
            for (int i = 0; i < 4; i++) {
                int r = row0 + warpM * 32 + mt * 16 + gId + (i >> 1) * 8;
                int c = col0 + warpN * 32 + nt * 8 + tig * 2 + (i & 1);
                if (c < N) {
                    float v = d[mt][nt][i];
                    if (b1)   v += b1[c];
                    if (b2)   v += b2[c];
                    if (add1) v += add1[(size_t)r * N + c];
                    if (act)  v = gelu_exact(v);
                    C[(size_t)r * ldc + c] = v;
                }
            }
        }
    }
}

// ---------------------------------------------------------------------------
// ATD: softmax probs P[ROWS][64] + argmax tkid. One warp per token.
// ---------------------------------------------------------------------------
__global__ void atd_kernel(const float* __restrict__ qatd, const float* __restrict__ kkn,
                           const float* __restrict__ scale,
                           float* __restrict__ P, int* __restrict__ tkid) {
    int t = (blockIdx.x * blockDim.x + threadIdx.x) >> 5;
    int lane = threadIdx.x & 31;
    if (t >= ROWS) return;
    int b = t >> 12;
    float q = (lane < RDIM) ? qatd[(size_t)t * RDIM + lane] : 0.f;
    float ss = warp_sum(q * q);
    float qn = q * (1.f / fmaxf(sqrtf(ss), 1e-12f));
    const float* kb = kkn + (size_t)b * MTOK * RDIM;
    float s0 = 0.f, s1 = 0.f;
    #pragma unroll
    for (int d = 0; d < RDIM; d++) {
        float qd = __shfl_sync(0xffffffffu, qn, d);
        s0 += qd * kb[lane * RDIM + d];
        s1 += qd * kb[(lane + 32) * RDIM + d];
    }
    float sc = fminf(fmaxf(scale[0], 0.f), 3.f);
    float ls = 1.f + sc * 4.15888308335967186f;  // log(64)
    s0 *= ls; s1 *= ls;
    float mv = fmaxf(s0, s1);
    int mi = (s0 >= s1) ? lane : lane + 32;
    #pragma unroll
    for (int o = 16; o; o >>= 1) {
        float ov = __shfl_xor_sync(0xffffffffu, mv, o);
        int   oi = __shfl_xor_sync(0xffffffffu, mi, o);
        if (ov > mv || (ov == mv && oi < mi)) { mv = ov; mi = oi; }
    }
    float p0 = __expf(s0 - mv), p1 = __expf(s1 - mv);
    float sum = warp_sum(p0 + p1);
    float inv = 1.f / sum;
    P[(size_t)t * MTOK + lane]      = p0 * inv;
    P[(size_t)t * MTOK + lane + 32] = p1 * inv;
    if (lane == 0) tkid[t] = mi;
}

// ---------------------------------------------------------------------------
// Single-pass stable counting sort scatter: block = (batch, bin).
// Each block scans all 4096 ids; position = #(tk<bin) + #(tk==bin before i).
// ---------------------------------------------------------------------------
__global__ void sortscatter_kernel(const int* __restrict__ tkid, int* __restrict__ sidx) {
    int b = blockIdx.x >> 6, bin = blockIdx.x & 63;
    const int* tk = tkid + b * NTOK;
    __shared__ int sc[256];
    int t = threadIdx.x;
    int start = t * 16;
    int eq = 0, less = 0;
    int vals[16];
    #pragma unroll
    for (int k = 0; k < 16; k++) {
        vals[k] = tk[start + k];
        eq += (vals[k] == bin);
        less += (vals[k] < bin);
    }
    sc[t] = (less << 16) | eq;
    __syncthreads();
    #pragma unroll
    for (int d = 1; d < 256; d <<= 1) {
        int v = (t >= d) ? sc[t - d] : 0;
        __syncthreads();
        sc[t] += v;
        __syncthreads();
    }
    int base = sc[255] >> 16;                       // total #(tk < bin)
    int pos = base + (sc[t] & 0xffff) - eq;         // exclusive prefix of eq
    #pragma unroll
    for (int k = 0; k < 16; k++)
        if (vals[k] == bin) sidx[b * NTOK + pos++] = start + k;
}

// ---------------------------------------------------------------------------
// AC_MSA grouped attention (f32x2, chunked online softmax CH=16)
// ---------------------------------------------------------------------------
__global__ void acmsa_kernel(const float* __restrict__ qkv, const int* __restrict__ sidx,
                             float* __restrict__ yout) {
    int bi = blockIdx.x;
    int hh = bi % HEADS;
    int g  = (bi / HEADS) % NG;
    int b  = bi / (HEADS * NG);
    int t = threadIdx.x;
    __shared__ __align__(16) float Ks[GS][32], Vs[GS][32];
    int rn = sidx[b * NTOK + g * GS + t];
    const float* base = qkv + ((size_t)(b * NTOK + rn)) * QKVW + hh * HD;
    const float scale = 0.18257418583505536f;   // 30^-0.5
    float q[32];
    #pragma unroll
    for (int d = 0; d < HD; d++) {
        q[d] = base[d] * scale;
        Ks[t][d] = base[180 + d];
        Vs[t][d] = base[360 + d];
    }
    q[30] = q[31] = 0.f;
    Ks[t][30] = Ks[t][31] = 0.f;
    Vs[t][30] = Vs[t][31] = 0.f;
    unsigned long long q2[16];
    #pragma unroll
    for (int i = 0; i < 16; i++) q2[i] = pack2(q[2*i], q[2*i+1]);
    __syncthreads();
    float m = -1e30f, l = 0.f;
    unsigned long long acc2[16];
    #pragma unroll
    for (int i = 0; i < 16; i++) acc2[i] = pack2(0.f, 0.f);
    for (int jc = 0; jc < GS; jc += 16) {
        float scv[16];
        #pragma unroll
        for (int u = 0; u < 16; u++) {
            const unsigned long long* k2 = (const unsigned long long*)Ks[jc + u];
            unsigned long long s2 = pack2(0.f, 0.f);
            #pragma unroll
            for (int i = 0; i < 16; i++) fma2(s2, q2[i], k2[i]);
            float slo, shi; unpack2(s2, slo, shi);
            scv[u] = slo + shi;
        }
        float cm = scv[0];
        #pragma unroll
        for (int u = 1; u < 16; u++) cm = fmaxf(cm, scv[u]);
        float mn = fmaxf(m, cm);
        float co = __expf(m - mn);
        m = mn;
        l *= co;
        unsigned long long co2 = pack2(co, co);
        #pragma unroll
        for (int i = 0; i < 16; i++) acc2[i] = mul2(acc2[i], co2);
        #pragma unroll
        for (int u = 0; u < 16; u++) {
            float p = __expf(scv[u] - mn);
            l += p;
            unsigned long long p2 = pack2(p, p);
            const unsigned long long* v2 = (const unsigned long long*)Vs[jc + u];
            #pragma unroll
            for (int i = 0; i < 16; i++) fma2(acc2[i], p2, v2[i]);
        }
    }
    float inv = 1.f / l;
    float* orow = yout + ((size_t)(b * NTOK + rn)) * DIMC + hh * HD;
    #pragma unroll
    for (int i = 0; i < 15; i++) {
        float lo, hi; unpack2(acc2[i], lo, hi);
        orow[2*i] = lo * inv;
        orow[2*i+1] = hi * inv;
    }
}

// ---------------------------------------------------------------------------
// Window attention (f32x2, chunked online softmax CH=16)
// ---------------------------------------------------------------------------
__global__ void winattn_kernel(const float* __restrict__ qkv, float* __restrict__ yout) {
    extern __shared__ float sm[];
    float* Ks = sm;
    float* Vs = sm + WINN * 32;
    int bi = blockIdx.x;
    int hh = bi % HEADS;
    int wdx = bi / HEADS;
    int b = wdx >> 4;
    int wy = (wdx >> 2) & 3;
    int wx = wdx & 3;
    int t = threadIdx.x;
    int iy = t >> 4, ix = t & 15;
    int nidx = (wy * WS + iy) * WW + (wx * WS + ix);
    size_t rowbase = ((size_t)(b * NTOK + nidx)) * QKVW + hh * HD;
    const float scale = 0.18257418583505536f;
    float q[32];
    #pragma unroll
    for (int d = 0; d < HD; d++) {
        q[d] = qkv[rowbase + d] * scale;
        Ks[t * 32 + d] = qkv[rowbase + 180 + d];
        Vs[t * 32 + d] = qkv[rowbase + 360 + d];
    }
    q[30] = q[31] = 0.f;
    Ks[t * 32 + 30] = Ks[t * 32 + 31] = 0.f;
    Vs[t * 32 + 30] = Vs[t * 32 + 31] = 0.f;
    unsigned long long q2[16];
    #pragma unroll
    for (int i = 0; i < 16; i++) q2[i] = pack2(q[2*i], q[2*i+1]);
    __syncthreads();
    const float* brow = g_wbias + ((size_t)hh * WINN + t) * WINN;
    float m = -1e30f, l = 0.f;
    unsigned long long acc2[16];
    #pragma unroll
    for (int i = 0; i < 16; i++) acc2[i] = pack2(0.f, 0.f);
    for (int jc = 0; jc < WINN; jc += 16) {
        float scv[16];
        #pragma unroll
        for (int u = 0; u < 16; u++) {
            const unsigned long long* k2 = (const unsigned long long*)(Ks + (jc + u) * 32);
            unsigned long long s2 = pack2(0.f, 0.f);
            #pragma unroll
            for (int i = 0; i < 16; i++) fma2(s2, q2[i], k2[i]);
            float slo, shi; unpack2(s2, slo, shi);
            scv[u] = slo + shi + brow[jc + u];
        }
        float cm = scv[0];
        #pragma unroll
        for (int u = 1; u < 16; u++) cm = fmaxf(cm, scv[u]);
        float mn = fmaxf(m, cm);
        float co = __expf(m - mn);
        m = mn;
        l *= co;
        unsigned long long co2 = pack2(co, co);
        #pragma unroll
        for (int i = 0; i < 16; i++) acc2[i] = mul2(acc2[i], co2);
        #pragma unroll
        for (int u = 0; u < 16; u++) {
            float p = __expf(scv[u] - mn);
            l += p;
            unsigned long long p2 = pack2(p, p);
            const unsigned long long* v2 = (const unsigned long long*)(Vs + (jc + u) * 32);
            #pragma unroll
            for (int i = 0; i < 16; i++) fma2(acc2[i], p2, v2[i]);
        }
    }
    float inv = 1.f / l;
    float* orow = yout + ((size_t)(b * NTOK + nidx)) * DIMC + hh * HD;
    #pragma unroll
    for (int i = 0; i < 15; i++) {
        float lo, hi; unpack2(acc2[i], lo, hi);
        orow[2*i] = lo * inv;
        orow[2*i+1] = hi * inv;
    }
}

// ---------------------------------------------------------------------------
// Gather per-token dictionary features into hc[:, 360:424]
// ---------------------------------------------------------------------------
__global__ void gathertd_kernel(const float* __restrict__ tdproj, const int* __restrict__ tkid,
                                float* __restrict__ hc) {
    int e = blockIdx.x * blockDim.x + threadIdx.x;
    if (e < ROWS * DTD) {
        int r = e >> 6, j = e & 63;
        int b = r >> 12;
        hc[(size_t)r * CFF + MLP_HID + j] = tdproj[((size_t)b * MTOK + tkid[r]) * DTD + j];
    }
}

// ---------------------------------------------------------------------------
// Depthwise 5x5 conv, tiled: 16x16 pixels x 8 channels per block.
// ---------------------------------------------------------------------------
#define DWCH 8
__global__ void dwconv_kernel(const float* __restrict__ hc, const float* __restrict__ w,
                              const float* __restrict__ bias, float* __restrict__ hc2) {
    __shared__ float smd[20 * 20 * DWCH];
    __shared__ float wsm[25][DWCH];
    __shared__ float bsm[DWCH];
    int tid = threadIdx.x;
    int c0 = blockIdx.y * DWCH;
    int b  = blockIdx.z;
    int tileY = (blockIdx.x >> 2) * 16, tileX = (blockIdx.x & 3) * 16;
    if (tid < 200) { int t5 = tid % 25, j = tid / 25; wsm[t5][j] = w[(c0 + j) * 25 + t5]; }
    if (tid < DWCH) bsm[tid] = bias[c0 + tid];
    for (int i = tid; i < 800; i += 256) {
        int cell = i >> 1, half = i & 1;
        int cy = cell / 20, cx = cell % 20;
        int gy = tileY + cy - 2, gx = tileX + cx - 2;
        float4 v = {0.f, 0.f, 0.f, 0.f};
        if (gy >= 0 && gy < 64 && gx >= 0 && gx < 64)
            v = *(const float4*)&hc[(((size_t)b << 12) + (gy << 6) + gx) * CFF + c0 + half * 4];
        *(float4*)&smd[cell * 8 + half * 4] = v;
    }
    __syncthreads();
    int ty = tid >> 4, tx = tid & 15;
    float acc[DWCH];
    #pragma unroll
    for (int j = 0; j < DWCH; j++) acc[j] = 0.f;
    #pragma unroll
    for (int ky = 0; ky < 5; ky++) {
        #pragma unroll
        for (int kx = 0; kx < 5; kx++) {
            const float* cp = &smd[((ty + ky) * 20 + tx + kx) * 8];
            float4 a0 = *(const float4*)cp;
            float4 a1 = *(const float4*)(cp + 4);
            int t5 = ky * 5 + kx;
            acc[0] += a0.x * wsm[t5][0];
            acc[1] += a0.y * wsm[t5][1];
            acc[2] += a0.z * wsm[t5][2];
            acc[3] += a0.w * wsm[t5][3];
            acc[4] += a1.x * wsm[t5][4];
            acc[5] += a1.y * wsm[t5][5];
            acc[6] += a1.z * wsm[t5][6];
            acc[7] += a1.w * wsm[t5][7];
        }
    }
    const float* ctr = &smd[((ty + 2) * 20 + tx + 2) * 8];
    size_t idx = (((size_t)b << 12) + ((size_t)(tileY + ty) << 6) + (tileX + tx)) * CFF + c0;
    float4 o0, o1;
    o0.x = ctr[0] + gelu_exact(acc[0] + bsm[0]);
    o0.y = ctr[1] + gelu_exact(acc[1] + bsm[1]);
    o0.z = ctr[2] + gelu_exact(acc[2] + bsm[2]);
    o0.w = ctr[3] + gelu_exact(acc[3] + bsm[3]);
    o1.x = ctr[4] + gelu_exact(acc[4] + bsm[4]);
    o1.y = ctr[5] + gelu_exact(acc[5] + bsm[5]);
    o1.z = ctr[6] + gelu_exact(acc[6] + bsm[6]);
    o1.w = ctr[7] + gelu_exact(acc[7] + bsm[7]);
    *(float4*)&hc2[idx] = o0;
    *(float4*)&hc2[idx + 4] = o1;
}

// ---------------------------------------------------------------------------
// Launch (ordered so launch #6 = winattn for ncu -s 5 -c 1 visibility)
// ---------------------------------------------------------------------------
extern "C" void kernel_launch(void* const* d_in, const int* in_sizes, int n_in,
                              void* d_out, int out_size) {
    const float* x        = (const float*)d_in[0];
    const float* td       = (const float*)d_in[1];
    const float* n1g      = (const float*)d_in[2];
    const float* n1b      = (const float*)d_in[3];
    const float* wqkv_w   = (const float*)d_in[4];
    const float* wqkv_b   = (const float*)d_in[5];
    const float* atd_wq_w = (const float*)d_in[6];
    const float* atd_wq_b = (const float*)d_in[7];
    const float* atd_wk_w = (const float*)d_in[8];
    const float* atd_wk_b = (const float*)d_in[9];
    const float* atd_wv_w = (const float*)d_in[10];
    const float* atd_wv_b = (const float*)d_in[11];
    const float* atd_sc   = (const float*)d_in[12];
    const float* aca_w    = (const float*)d_in[13];
    const float* aca_b    = (const float*)d_in[14];
    const float* win_rpb  = (const float*)d_in[15];
    const float* win_w    = (const float*)d_in[16];
    const float* win_b    = (const float*)d_in[17];
    const float* fctd_w   = (const float*)d_in[18];
    const float* fctd_b   = (const float*)d_in[19];
    const float* fc1_w    = (const float*)d_in[20];
    const float* fc1_b    = (const float*)d_in[21];
    const float* dw_w     = (const float*)d_in[22];
    const float* dw_b     = (const float*)d_in[23];
    const float* fc2_w    = (const float*)d_in[24];
    const float* fc2_b    = (const float*)d_in[25];
    const float* n2g      = (const float*)d_in[26];
    const float* n2b      = (const float*)d_in[27];
    const int*   rpi      = (const int*)d_in[28];
    float* out = (float*)d_out;

    float *xn, *qkv, *qatd, *kkn, *vv, *tdpr, *patd, *yaca, *ywin, *xsum, *x2n, *hc, *hc2;
    int *tkid, *sidx;
    cudaGetSymbolAddress((void**)&xn,   g_xn);
    cudaGetSymbolAddress((void**)&qkv,  g_qkv);
    cudaGetSymbolAddress((void**)&qatd, g_qatd);
    cudaGetSymbolAddress((void**)&kkn,  g_kkn);
    cudaGetSymbolAddress((void**)&vv,   g_vv);
    cudaGetSymbolAddress((void**)&tdpr, g_tdpr);
    cudaGetSymbolAddress((void**)&patd, g_patd);
    cudaGetSymbolAddress((void**)&yaca, g_yaca);
    cudaGetSymbolAddress((void**)&ywin, g_ywin);
    cudaGetSymbolAddress((void**)&xsum, g_xsum);
    cudaGetSymbolAddress((void**)&x2n,  g_x2n);
    cudaGetSymbolAddress((void**)&hc,   g_hc);
    cudaGetSymbolAddress((void**)&hc2,  g_hc2);
    cudaGetSymbolAddress((void**)&tkid, g_tkid);
    cudaGetSymbolAddress((void**)&sidx, g_sidx);

    // 1. dictionary projections (kk l2-normalized, vv, td_proj) — one kernel
    dict_kernel<<<BATCH*MTOK, 256>>>(td, atd_wk_w, atd_wk_b, atd_wv_w, atd_wv_b,
                                     fctd_w, fctd_b, kkn, vv, tdpr);
    // 2. window bias expansion
    wbias_kernel<<<WINN*WINN/256, 256>>>(rpi, win_rpb);
    // 3. LN1 (+ fused q_atd projection)
    ln_kernel<<<ROWS/8, 256>>>(x, n1g, n1b, xn, atd_wq_w, atd_wq_b, qatd);
    // 4. qkv = xn @ wqkv + b
    gemm_tc<<<dim3(9, ROWS/128), 256>>>(xn, wqkv_w, DIMC, nullptr, nullptr, 0,
                                        nullptr, nullptr, 0, 0,
                                        wqkv_b, nullptr, nullptr,
                                        qkv, ROWS, QKVW, QKVW, 0);
    // 5. ATD probs + tk_id
    atd_kernel<<<ROWS/8, 256>>>(qatd, kkn, atd_sc, patd, tkid);
    // 6. window attention  (<- ncu captures this launch)
    cudaFuncSetAttribute(winattn_kernel, cudaFuncAttributeMaxDynamicSharedMemorySize, 65536);
    winattn_kernel<<<NWIN*HEADS, 256, 65536>>>(qkv, ywin);
    // 7. single-pass stable sort scatter
    sortscatter_kernel<<<BATCH*MTOK, 256>>>(tkid, sidx);
    // 8. grouped attention
    acmsa_kernel<<<BATCH*NG*HEADS, 128>>>(qkv, sidx, yaca);
    // 9. xsum = x + P@vv (batched) + yaca@aca_w + ywin@win_w + biases
    gemm_tc<<<dim3(3, ROWS/128), 256>>>(yaca, aca_w, DIMC, ywin, win_w, DIMC,
                                        patd, vv, (long)MTOK*DIMC, MTOK,
                                        aca_b, win_b, x,
                                        xsum, ROWS, DIMC, DIMC, 0);
    // 10. LN2
    ln_kernel<<<ROWS/8, 256>>>(xsum, n2g, n2b, x2n, nullptr, nullptr, nullptr);
    // 11. fc1 + GELU into hc[:, 0:360]
    gemm_tc<<<dim3(6, ROWS/128), 256>>>(x2n, fc1_w, DIMC, nullptr, nullptr, 0,
                                        nullptr, nullptr, 0, 0,
                                        fc1_b, nullptr, nullptr,
                                        hc, ROWS, MLP_HID, CFF, 1);
    // 12. gather td features into hc[:, 360:424]
    gathertd_kernel<<<ROWS*DTD/256, 256>>>(tdpr, tkid, hc);
    // 13. depthwise conv + gelu + residual (tiled)
    dwconv_kernel<<<dim3(16, CFF/DWCH, BATCH), 256>>>(hc, dw_w, dw_b, hc2);
    // 14. out = xsum + hc2 @ fc2_w + fc2_b
    gemm_tc<<<dim3(3, ROWS/128), 256>>>(hc2, fc2_w, CFF, nullptr, nullptr, 0,
                                        nullptr, nullptr, 0, 0,
                                        fc2_b, nullptr, xsum,
                                        out, ROWS, DIMC, DIMC, 0);
}

// round 6
// speedup vs baseline: 1.7877x; 1.0637x over previous
#include <cuda_runtime.h>
#include <cuda_bf16.h>
#include <math.h>

// ---------------------------------------------------------------------------
// Problem constants
// ---------------------------------------------------------------------------
#define BATCH 8
#define NTOK 4096
#define ROWS (BATCH*NTOK)
#define DIMC 180
#define HEADS 6
#define HD 30
#define QKVW 540
#define MTOK 64
#define RDIM 10
#define GS 128
#define NG 32
#define WS 16
#define WINN 256
#define NWIN 128
#define MLP_HID 360
#define DTD 64
#define CFF 424
#define HH 64
#define WW 64

// ---------------------------------------------------------------------------
// Scratch
// ---------------------------------------------------------------------------
__device__ float g_xn   [ROWS*DIMC];
__device__ float g_qkv  [ROWS*QKVW];
__device__ float g_qatd [ROWS*RDIM];
__device__ float g_kkn  [BATCH*MTOK*RDIM];
__device__ float g_vv   [BATCH*MTOK*DIMC];
__device__ float g_tdpr [BATCH*MTOK*DTD];
__device__ float g_patd [ROWS*MTOK];
__device__ int   g_tkid [ROWS];
__device__ int   g_sidx [ROWS];
__device__ float g_yaca [ROWS*DIMC];
__device__ float g_ywin [ROWS*DIMC];
__device__ float g_xsum [ROWS*DIMC];
__device__ float g_x2n  [ROWS*DIMC];
__device__ float g_hc   [ROWS*CFF];
__device__ float g_hc2  [ROWS*CFF];
__device__ float g_wbias[HEADS*WINN*WINN];

// ---------------------------------------------------------------------------
// Helpers
// ---------------------------------------------------------------------------
__device__ __forceinline__ float warp_sum(float v) {
    #pragma unroll
    for (int o = 16; o; o >>= 1) v += __shfl_xor_sync(0xffffffffu, v, o);
    return v;
}
__device__ __forceinline__ float gelu_exact(float v) {
    return 0.5f * v * (1.0f + erff(v * 0.70710678118654752440f));
}
__device__ __forceinline__ unsigned long long pack2(float lo, float hi) {
    unsigned long long r;
    asm("mov.b64 %0,{%1,%2};" : "=l"(r) : "f"(lo), "f"(hi));
    return r;
}
__device__ __forceinline__ void unpack2(unsigned long long v, float& lo, float& hi) {
    asm("mov.b64 {%0,%1},%2;" : "=f"(lo), "=f"(hi) : "l"(v));
}
__device__ __forceinline__ void fma2(unsigned long long& d, unsigned long long a,
                                     unsigned long long b) {
    asm("fma.rn.f32x2 %0,%1,%2,%0;" : "+l"(d) : "l"(a), "l"(b));
}
__device__ __forceinline__ unsigned long long mul2(unsigned long long a, unsigned long long b) {
    unsigned long long r;
    asm("mul.rn.f32x2 %0,%1,%2;" : "=l"(r) : "l"(a), "l"(b));
    return r;
}
__device__ __forceinline__ unsigned smem_u32(const void* p) {
    return (unsigned)__cvta_generic_to_shared(p);
}

// ---------------------------------------------------------------------------
// Fused dictionary projections: per td row -> vv(180), tdpr(64), kkn(10, l2n)
// ---------------------------------------------------------------------------
__global__ void dict_kernel(const float* __restrict__ td,
                            const float* __restrict__ wk_w, const float* __restrict__ wk_b,
                            const float* __restrict__ wv_w, const float* __restrict__ wv_b,
                            const float* __restrict__ ftd_w, const float* __restrict__ ftd_b,
                            float* __restrict__ kkn, float* __restrict__ vv,
                            float* __restrict__ tdpr) {
    int r = blockIdx.x;                 // 0..511
    __shared__ float as[DIMC];
    __shared__ float kbuf[RDIM];
    int tid = threadIdx.x;
    const float* ar = td + (size_t)r * DIMC;
    if (tid < DIMC) as[tid] = ar[tid];
    __syncthreads();
    if (tid < DIMC) {
        float acc = wv_b[tid];
        #pragma unroll 4
        for (int k = 0; k < DIMC; k++) acc += as[k] * wv_w[(size_t)k * DIMC + tid];
        vv[(size_t)r * DIMC + tid] = acc;
    } else if (tid < DIMC + DTD) {
        int c = tid - DIMC;
        float acc = ftd_b[c];
        #pragma unroll 4
        for (int k = 0; k < DIMC; k++) acc += as[k] * ftd_w[(size_t)k * DTD + c];
        tdpr[(size_t)r * DTD + c] = acc;
    } else if (tid < DIMC + DTD + RDIM) {
        int c = tid - DIMC - DTD;
        float acc = wk_b[c];
        #pragma unroll 4
        for (int k = 0; k < DIMC; k++) acc += as[k] * wk_w[(size_t)k * RDIM + c];
        kbuf[c] = acc;
    }
    __syncthreads();
    if (tid >= DIMC + DTD && tid < DIMC + DTD + RDIM) {
        int c = tid - DIMC - DTD;
        float ss = 0.f;
        #pragma unroll
        for (int j = 0; j < RDIM; j++) ss += kbuf[j] * kbuf[j];
        float inv = 1.f / fmaxf(sqrtf(ss), 1e-12f);
        kkn[(size_t)r * RDIM + c] = kbuf[c] * inv;
    }
}

// ---------------------------------------------------------------------------
// Window attention bias expansion
// ---------------------------------------------------------------------------
__global__ void wbias_kernel(const int* __restrict__ rpi, const float* __restrict__ rpb) {
    int e = blockIdx.x * blockDim.x + threadIdx.x;
    if (e < WINN * WINN) {
        int idx = rpi[e];
        #pragma unroll
        for (int h = 0; h < HEADS; h++) g_wbias[h * WINN * WINN + e] = rpb[idx * HEADS + h];
    }
}

// ---------------------------------------------------------------------------
// LayerNorm (+ optional fused 10-dim q projection): one warp per row.
// ---------------------------------------------------------------------------
__global__ void ln_kernel(const float* __restrict__ x, const float* __restrict__ g,
                          const float* __restrict__ b, float* __restrict__ out,
                          const float* __restrict__ wq, const float* __restrict__ bq,
                          float* __restrict__ qout) {
    __shared__ float ws[1920];
    __shared__ float bqs[16];
    int tid = threadIdx.x;
    if (wq) {
        for (int i = tid; i < 1920; i += 256) ws[i] = (i < DIMC * RDIM) ? wq[i] : 0.f;
        if (tid < RDIM) bqs[tid] = bq[tid];
        __syncthreads();
    }
    int row = (blockIdx.x * blockDim.x + tid) >> 5;
    if (row >= ROWS) return;
    int lane = tid & 31;
    const float* xr = x + (size_t)row * DIMC;
    float v[6], s = 0.f, s2 = 0.f;
    #pragma unroll
    for (int k = 0; k < 6; k++) {
        int c = lane + k * 32;
        v[k] = (c < DIMC) ? xr[c] : 0.f;
        s += v[k]; s2 += v[k] * v[k];
    }
    s = warp_sum(s); s2 = warp_sum(s2);
    float mu = s * (1.f / DIMC);
    float var = s2 * (1.f / DIMC) - mu * mu;
    float rstd = rsqrtf(var + 1e-5f);
    float nv[6];
    float* orow = out + (size_t)row * DIMC;
    #pragma unroll
    for (int k = 0; k < 6; k++) {
        int c = lane + k * 32;
        nv[k] = (c < DIMC) ? ((v[k] - mu) * rstd * g[c] + b[c]) : 0.f;
        if (c < DIMC) orow[c] = nv[k];
    }
    if (wq) {
        float myq = 0.f;
        #pragma unroll
        for (int o = 0; o < RDIM; o++) {
            float p = 0.f;
            #pragma unroll
            for (int k = 0; k < 6; k++) p += nv[k] * ws[(lane + 32 * k) * RDIM + o];
            p = warp_sum(p);
            if (lane == o) myq = p + bqs[o];
        }
        if (lane < RDIM) qout[(size_t)row * RDIM + lane] = myq;
    }
}

// ---------------------------------------------------------------------------
// Tensor-core tf32 GEMM with cp.async double-buffering; up to 3 fused passes.
// ---------------------------------------------------------------------------
struct GPass { const float* A; const float* W; int K; int kt; };

__global__ __launch_bounds__(256) void gemm_tc(
        const float* __restrict__ A1, const float* __restrict__ W1, int K1,
        const float* __restrict__ A2, const float* __restrict__ W2, int K2,
        const float* __restrict__ A3, const float* __restrict__ W3base, long w3_stride, int K3,
        const float* __restrict__ b1, const float* __restrict__ b2,
        const float* __restrict__ add1,
        float* __restrict__ C, int M, int N, int ldc, int act) {
    __shared__ float As[2][128][28];
    __shared__ float Ws[2][16][68];
    int tid  = threadIdx.x;
    int lane = tid & 31;
    int warp = tid >> 5;
    int warpM = warp & 3;
    int warpN = warp >> 2;
    int gId = lane >> 2;
    int tig = lane & 3;
    int row0 = blockIdx.y * 128;
    int col0 = blockIdx.x * 64;

    GPass ps[3];
    int np = 0;
    if (A1 && K1 > 0) ps[np++] = {A1, W1, K1, (K1 + 15) >> 4};
    if (A2 && K2 > 0) ps[np++] = {A2, W2, K2, (K2 + 15) >> 4};
    if (A3 && K3 > 0) ps[np++] = {A3, W3base + (size_t)(row0 >> 12) * w3_stride, K3, (K3 + 15) >> 4};
    int total = 0;
    for (int p = 0; p < np; p++) total += ps[p].kt;

    auto copy_tile = [&](int gi, int buf) {
        int p = 0, loc = gi;
        while (loc >= ps[p].kt) { loc -= ps[p].kt; p++; }
        const float* A = ps[p].A;
        const float* W = ps[p].W;
        int K = ps[p].K;
        int k0 = loc << 4;
        #pragma unroll
        for (int f = 0; f < 2; f++) {
            int cch = tid + f * 256;
            int m = cch >> 2, kk = (cch & 3) << 2;
            int gk = k0 + kk;
            int rem = K - gk;
            int bytes = (rem <= 0) ? 0 : ((rem >= 4) ? 16 : rem * 4);
            const float* src = bytes ? (A + (size_t)(row0 + m) * K + gk) : A;
            unsigned dst = smem_u32(&As[buf][m][kk]);
            asm volatile("cp.async.ca.shared.global [%0], [%1], 16, %2;"
                         :: "r"(dst), "l"(src), "r"(bytes));
        }
        {
            int kk = tid >> 4, n4 = (tid & 15) << 2;
            int gk = k0 + kk, gn = col0 + n4;
            int bytes = 0;
            if (gk < K) {
                int nb = N - gn;
                bytes = (nb <= 0) ? 0 : ((nb >= 4) ? 16 : nb * 4);
            }
            const float* src = bytes ? (W + (size_t)gk * N + gn) : W;
            unsigned dst = smem_u32(&Ws[buf][kk][n4]);
            asm volatile("cp.async.ca.shared.global [%0], [%1], 16, %2;"
                         :: "r"(dst), "l"(src), "r"(bytes));
        }
    };

    float d[2][4][4];
    #pragma unroll
    for (int mt = 0; mt < 2; mt++)
        #pragma unroll
        for (int nt = 0; nt < 4; nt++)
            #pragma unroll
            for (int i = 0; i < 4; i++) d[mt][nt][i] = 0.f;

    copy_tile(0, 0);
    asm volatile("cp.async.commit_group;");
    for (int i = 0; i < total; i++) {
        if (i + 1 < total) {
            copy_tile(i + 1, (i + 1) & 1);
            asm volatile("cp.async.commit_group;");
            asm volatile("cp.async.wait_group 1;");
        } else {
            asm volatile("cp.async.wait_group 0;");
        }
        __syncthreads();
        int buf = i & 1;
        #pragma unroll
        for (int ks = 0; ks < 2; ks++) {
            int kb = ks * 8;
            unsigned a[2][4], bfr[4][2];
            #pragma unroll
            for (int mt = 0; mt < 2; mt++) {
                int m0 = warpM * 32 + mt * 16;
                a[mt][0] = __float_as_uint(As[buf][m0 + gId    ][kb + tig    ]);
                a[mt][1] = __float_as_uint(As[buf][m0 + gId + 8][kb + tig    ]);
                a[mt][2] = __float_as_uint(As[buf][m0 + gId    ][kb + tig + 4]);
                a[mt][3] = __float_as_uint(As[buf][m0 + gId + 8][kb + tig + 4]);
            }
            #pragma unroll
            for (int nt = 0; nt < 4; nt++) {
                int n0 = warpN * 32 + nt * 8;
                bfr[nt][0] = __float_as_uint(Ws[buf][kb + tig    ][n0 + gId]);
                bfr[nt][1] = __float_as_uint(Ws[buf][kb + tig + 4][n0 + gId]);
            }
            #pragma unroll
            for (int mt = 0; mt < 2; mt++)
                #pragma unroll
                for (int nt = 0; nt < 4; nt++) {
                    asm volatile(
                        "mma.sync.aligned.m16n8k8.row.col.f32.tf32.tf32.f32 "
                        "{%0,%1,%2,%3},{%4,%5,%6,%7},{%8,%9},{%0,%1,%2,%3};"
                        : "+f"(d[mt][nt][0]), "+f"(d[mt][nt][1]),
                          "+f"(d[mt][nt][2]), "+f"(d[mt][nt][3])
                        : "r"(a[mt][0]), "r"(a[mt][1]), "r"(a[mt][2]), "r"(a[mt][3]),
                          "r"(bfr[nt][0]), "r"(bfr[nt][1]));
                }
        }
        __syncthreads();
    }

    #pragma unroll
    for (int mt = 0; mt < 2; mt++) {
        #pragma unroll
        for (int nt = 0; nt < 4; nt++) {
            #pragma unroll
            for (int i = 0; i < 4; i++) {
                int r = row0 + warpM * 32 + mt * 16 + gId + (i >> 1) * 8;
                int c = col0 + warpN * 32 + nt * 8 + tig * 2 + (i & 1);
                if (c < N) {
                    float v = d[mt][nt][i];
                    if (b1)   v += b1[c];
                    if (b2)   v += b2[c];
                    if (add1) v += add1[(size_t)r * N + c];
                    if (act)  v = gelu_exact(v);
                    C[(size_t)r * ldc + c] = v;
                }
            }
        }
    }
}

// ---------------------------------------------------------------------------
// ATD: softmax probs P[ROWS][64] + argmax tkid. One warp per token.
// ---------------------------------------------------------------------------
__global__ void atd_kernel(const float* __restrict__ qatd, const float* __restrict__ kkn,
                           const float* __restrict__ scale,
                           float* __restrict__ P, int* __restrict__ tkid) {
    int t = (blockIdx.x * blockDim.x + threadIdx.x) >> 5;
    int lane = threadIdx.x & 31;
    if (t >= ROWS) return;
    int b = t >> 12;
    float q = (lane < RDIM) ? qatd[(size_t)t * RDIM + lane] : 0.f;
    float ss = warp_sum(q * q);
    float qn = q * (1.f / fmaxf(sqrtf(ss), 1e-12f));
    const float* kb = kkn + (size_t)b * MTOK * RDIM;
    float s0 = 0.f, s1 = 0.f;
    #pragma unroll
    for (int d = 0; d < RDIM; d++) {
        float qd = __shfl_sync(0xffffffffu, qn, d);
        s0 += qd * kb[lane * RDIM + d];
        s1 += qd * kb[(lane + 32) * RDIM + d];
    }
    float sc = fminf(fmaxf(scale[0], 0.f), 3.f);
    float ls = 1.f + sc * 4.15888308335967186f;  // log(64)
    s0 *= ls; s1 *= ls;
    float mv = fmaxf(s0, s1);
    int mi = (s0 >= s1) ? lane : lane + 32;
    #pragma unroll
    for (int o = 16; o; o >>= 1) {
        float ov = __shfl_xor_sync(0xffffffffu, mv, o);
        int   oi = __shfl_xor_sync(0xffffffffu, mi, o);
        if (ov > mv || (ov == mv && oi < mi)) { mv = ov; mi = oi; }
    }
    float p0 = __expf(s0 - mv), p1 = __expf(s1 - mv);
    float sum = warp_sum(p0 + p1);
    float inv = 1.f / sum;
    P[(size_t)t * MTOK + lane]      = p0 * inv;
    P[(size_t)t * MTOK + lane + 32] = p1 * inv;
    if (lane == 0) tkid[t] = mi;
}

// ---------------------------------------------------------------------------
// Single-pass stable counting sort scatter: block = (batch, bin).
// ---------------------------------------------------------------------------
__global__ void sortscatter_kernel(const int* __restrict__ tkid, int* __restrict__ sidx) {
    int b = blockIdx.x >> 6, bin = blockIdx.x & 63;
    const int* tk = tkid + b * NTOK;
    __shared__ int sc[256];
    int t = threadIdx.x;
    int start = t * 16;
    int eq = 0, less = 0;
    int vals[16];
    #pragma unroll
    for (int k = 0; k < 16; k++) {
        vals[k] = tk[start + k];
        eq += (vals[k] == bin);
        less += (vals[k] < bin);
    }
    sc[t] = (less << 16) | eq;
    __syncthreads();
    #pragma unroll
    for (int d = 1; d < 256; d <<= 1) {
        int v = (t >= d) ? sc[t - d] : 0;
        __syncthreads();
        sc[t] += v;
        __syncthreads();
    }
    int base = sc[255] >> 16;
    int pos = base + (sc[t] & 0xffff) - eq;
    #pragma unroll
    for (int k = 0; k < 16; k++)
        if (vals[k] == bin) sidx[b * NTOK + pos++] = start + k;
}

// ---------------------------------------------------------------------------
// AC_MSA grouped attention: cooperative coalesced K/V load + f32x2 chunked
// online softmax.
// ---------------------------------------------------------------------------
__global__ __launch_bounds__(128) void acmsa_kernel(
        const float* __restrict__ qkv, const int* __restrict__ sidx,
        float* __restrict__ yout) {
    int bi = blockIdx.x;
    int hh = bi % HEADS;
    int g  = (bi / HEADS) % NG;
    int b  = bi / (HEADS * NG);
    int t = threadIdx.x;
    int lane = t & 31;
    int wb = (t >> 5) << 5;            // warp base row
    __shared__ __align__(16) float Ks[GS][32], Vs[GS][32];
    int rn = sidx[b * NTOK + g * GS + t];
    // --- cooperative coalesced K/V fill: warp fills its 32 rows ---
    #pragma unroll 4
    for (int u = 0; u < 32; u++) {
        int r_u = __shfl_sync(0xffffffffu, rn, u);
        size_t rb = ((size_t)(b * NTOK + r_u)) * QKVW + hh * HD;
        int rr = wb + u;
        float kv = 0.f, vv_ = 0.f;
        if (lane < HD) {
            kv  = qkv[rb + 180 + lane];
            vv_ = qkv[rb + 360 + lane];
        }
        Ks[rr][lane] = kv;
        Vs[rr][lane] = vv_;
    }
    // --- per-thread q (float2) ---
    const float scale = 0.18257418583505536f;   // 30^-0.5
    size_t qbase = ((size_t)(b * NTOK + rn)) * QKVW + hh * HD;
    const float2* qp = (const float2*)(qkv + qbase);
    unsigned long long q2[16];
    #pragma unroll
    for (int i = 0; i < 15; i++) {
        float2 v = qp[i];
        q2[i] = pack2(v.x * scale, v.y * scale);
    }
    q2[15] = pack2(0.f, 0.f);
    __syncthreads();
    float m = -1e30f, l = 0.f;
    unsigned long long acc2[16];
    #pragma unroll
    for (int i = 0; i < 16; i++) acc2[i] = pack2(0.f, 0.f);
    for (int jc = 0; jc < GS; jc += 16) {
        float scv[16];
        #pragma unroll
        for (int u = 0; u < 16; u++) {
            const unsigned long long* k2 = (const unsigned long long*)Ks[jc + u];
            unsigned long long s2 = pack2(0.f, 0.f);
            #pragma unroll
            for (int i = 0; i < 15; i++) fma2(s2, q2[i], k2[i]);
            float slo, shi; unpack2(s2, slo, shi);
            scv[u] = slo + shi;
        }
        float cm = scv[0];
        #pragma unroll
        for (int u = 1; u < 16; u++) cm = fmaxf(cm, scv[u]);
        float mn = fmaxf(m, cm);
        float co = __expf(m - mn);
        m = mn;
        l *= co;
        unsigned long long co2 = pack2(co, co);
        #pragma unroll
        for (int i = 0; i < 15; i++) acc2[i] = mul2(acc2[i], co2);
        #pragma unroll
        for (int u = 0; u < 16; u++) {
            float p = __expf(scv[u] - mn);
            l += p;
            unsigned long long p2 = pack2(p, p);
            const unsigned long long* v2 = (const unsigned long long*)Vs[jc + u];
            #pragma unroll
            for (int i = 0; i < 15; i++) fma2(acc2[i], p2, v2[i]);
        }
    }
    float inv = 1.f / l;
    float2* orow = (float2*)(yout + ((size_t)(b * NTOK + rn)) * DIMC + hh * HD);
    #pragma unroll
    for (int i = 0; i < 15; i++) {
        float lo, hi; unpack2(acc2[i], lo, hi);
        orow[i] = make_float2(lo * inv, hi * inv);
    }
}

// ---------------------------------------------------------------------------
// Window attention: cooperative coalesced K/V load + f32x2 chunked softmax.
// ---------------------------------------------------------------------------
__global__ __launch_bounds__(256) void winattn_kernel(const float* __restrict__ qkv,
                                                      float* __restrict__ yout) {
    extern __shared__ float sm[];
    float* Ks = sm;
    float* Vs = sm + WINN * 32;
    int bi = blockIdx.x;
    int hh = bi % HEADS;
    int wdx = bi / HEADS;
    int b = wdx >> 4;
    int wy = (wdx >> 2) & 3;
    int wx = wdx & 3;
    int t = threadIdx.x;
    int lane = t & 31;
    int wb = (t >> 5) << 5;
    // --- cooperative coalesced K/V fill: warp fills its 32 rows ---
    #pragma unroll 4
    for (int u = 0; u < 32; u++) {
        int rr = wb + u;
        int ny = (wy * WS + (rr >> 4)) * WW + wx * WS + (rr & 15);
        size_t rb = ((size_t)(b * NTOK + ny)) * QKVW + hh * HD;
        float kv = 0.f, vv_ = 0.f;
        if (lane < HD) {
            kv  = qkv[rb + 180 + lane];
            vv_ = qkv[rb + 360 + lane];
        }
        Ks[rr * 32 + lane] = kv;
        Vs[rr * 32 + lane] = vv_;
    }
    // --- per-thread q (float2) ---
    int iy = t >> 4, ix = t & 15;
    int nidx = (wy * WS + iy) * WW + (wx * WS + ix);
    size_t rowbase = ((size_t)(b * NTOK + nidx)) * QKVW + hh * HD;
    const float scale = 0.18257418583505536f;
    const float2* qp = (const float2*)(qkv + rowbase);
    unsigned long long q2[16];
    #pragma unroll
    for (int i = 0; i < 15; i++) {
        float2 v = qp[i];
        q2[i] = pack2(v.x * scale, v.y * scale);
    }
    q2[15] = pack2(0.f, 0.f);
    __syncthreads();
    const float* brow = g_wbias + ((size_t)hh * WINN + t) * WINN;
    float m = -1e30f, l = 0.f;
    unsigned long long acc2[16];
    #pragma unroll
    for (int i = 0; i < 16; i++) acc2[i] = pack2(0.f, 0.f);
    for (int jc = 0; jc < WINN; jc += 16) {
        float scv[16];
        #pragma unroll
        for (int u = 0; u < 16; u++) {
            const unsigned long long* k2 = (const unsigned long long*)(Ks + (jc + u) * 32);
            unsigned long long s2 = pack2(0.f, 0.f);
            #pragma unroll
            for (int i = 0; i < 15; i++) fma2(s2, q2[i], k2[i]);
            float slo, shi; unpack2(s2, slo, shi);
            scv[u] = slo + shi + brow[jc + u];
        }
        float cm = scv[0];
        #pragma unroll
        for (int u = 1; u < 16; u++) cm = fmaxf(cm, scv[u]);
        float mn = fmaxf(m, cm);
        float co = __expf(m - mn);
        m = mn;
        l *= co;
        unsigned long long co2 = pack2(co, co);
        #pragma unroll
        for (int i = 0; i < 15; i++) acc2[i] = mul2(acc2[i], co2);
        #pragma unroll
        for (int u = 0; u < 16; u++) {
            float p = __expf(scv[u] - mn);
            l += p;
            unsigned long long p2 = pack2(p, p);
            const unsigned long long* v2 = (const unsigned long long*)(Vs + (jc + u) * 32);
            #pragma unroll
            for (int i = 0; i < 15; i++) fma2(acc2[i], p2, v2[i]);
        }
    }
    float inv = 1.f / l;
    float2* orow = (float2*)(yout + ((size_t)(b * NTOK + nidx)) * DIMC + hh * HD);
    #pragma unroll
    for (int i = 0; i < 15; i++) {
        float lo, hi; unpack2(acc2[i], lo, hi);
        orow[i] = make_float2(lo * inv, hi * inv);
    }
}

// ---------------------------------------------------------------------------
// Gather per-token dictionary features into hc[:, 360:424]
// ---------------------------------------------------------------------------
__global__ void gathertd_kernel(const float* __restrict__ tdproj, const int* __restrict__ tkid,
                                float* __restrict__ hc) {
    int e = blockIdx.x * blockDim.x + threadIdx.x;
    if (e < ROWS * DTD) {
        int r = e >> 6, j = e & 63;
        int b = r >> 12;
        hc[(size_t)r * CFF + MLP_HID + j] = tdproj[((size_t)b * MTOK + tkid[r]) * DTD + j];
    }
}

// ---------------------------------------------------------------------------
// Depthwise 5x5 conv, tiled: 16x16 pixels x 8 channels per block.
// ---------------------------------------------------------------------------
#define DWCH 8
__global__ void dwconv_kernel(const float* __restrict__ hc, const float* __restrict__ w,
                              const float* __restrict__ bias, float* __restrict__ hc2) {
    __shared__ float smd[20 * 20 * DWCH];
    __shared__ float wsm[25][DWCH];
    __shared__ float bsm[DWCH];
    int tid = threadIdx.x;
    int c0 = blockIdx.y * DWCH;
    int b  = blockIdx.z;
    int tileY = (blockIdx.x >> 2) * 16, tileX = (blockIdx.x & 3) * 16;
    if (tid < 200) { int t5 = tid % 25, j = tid / 25; wsm[t5][j] = w[(c0 + j) * 25 + t5]; }
    if (tid < DWCH) bsm[tid] = bias[c0 + tid];
    for (int i = tid; i < 800; i += 256) {
        int cell = i >> 1, half = i & 1;
        int cy = cell / 20, cx = cell % 20;
        int gy = tileY + cy - 2, gx = tileX + cx - 2;
        float4 v = {0.f, 0.f, 0.f, 0.f};
        if (gy >= 0 && gy < 64 && gx >= 0 && gx < 64)
            v = *(const float4*)&hc[(((size_t)b << 12) + (gy << 6) + gx) * CFF + c0 + half * 4];
        *(float4*)&smd[cell * 8 + half * 4] = v;
    }
    __syncthreads();
    int ty = tid >> 4, tx = tid & 15;
    float acc[DWCH];
    #pragma unroll
    for (int j = 0; j < DWCH; j++) acc[j] = 0.f;
    #pragma unroll
    for (int ky = 0; ky < 5; ky++) {
        #pragma unroll
        for (int kx = 0; kx < 5; kx++) {
            const float* cp = &smd[((ty + ky) * 20 + tx + kx) * 8];
            float4 a0 = *(const float4*)cp;
            float4 a1 = *(const float4*)(cp + 4);
            int t5 = ky * 5 + kx;
            acc[0] += a0.x * wsm[t5][0];
            acc[1] += a0.y * wsm[t5][1];
            acc[2] += a0.z * wsm[t5][2];
            acc[3] += a0.w * wsm[t5][3];
            acc[4] += a1.x * wsm[t5][4];
            acc[5] += a1.y * wsm[t5][5];
            acc[6] += a1.z * wsm[t5][6];
            acc[7] += a1.w * wsm[t5][7];
        }
    }
    const float* ctr = &smd[((ty + 2) * 20 + tx + 2) * 8];
    size_t idx = (((size_t)b << 12) + ((size_t)(tileY + ty) << 6) + (tileX + tx)) * CFF + c0;
    float4 o0, o1;
    o0.x = ctr[0] + gelu_exact(acc[0] + bsm[0]);
    o0.y = ctr[1] + gelu_exact(acc[1] + bsm[1]);
    o0.z = ctr[2] + gelu_exact(acc[2] + bsm[2]);
    o0.w = ctr[3] + gelu_exact(acc[3] + bsm[3]);
    o1.x = ctr[4] + gelu_exact(acc[4] + bsm[4]);
    o1.y = ctr[5] + gelu_exact(acc[5] + bsm[5]);
    o1.z = ctr[6] + gelu_exact(acc[6] + bsm[6]);
    o1.w = ctr[7] + gelu_exact(acc[7] + bsm[7]);
    *(float4*)&hc2[idx] = o0;
    *(float4*)&hc2[idx + 4] = o1;
}

// ---------------------------------------------------------------------------
// Launch (launch #6 = winattn for ncu -s 5 -c 1 visibility)
// ---------------------------------------------------------------------------
extern "C" void kernel_launch(void* const* d_in, const int* in_sizes, int n_in,
                              void* d_out, int out_size) {
    const float* x        = (const float*)d_in[0];
    const float* td       = (const float*)d_in[1];
    const float* n1g      = (const float*)d_in[2];
    const float* n1b      = (const float*)d_in[3];
    const float* wqkv_w   = (const float*)d_in[4];
    const float* wqkv_b   = (const float*)d_in[5];
    const float* atd_wq_w = (const float*)d_in[6];
    const float* atd_wq_b = (const float*)d_in[7];
    const float* atd_wk_w = (const float*)d_in[8];
    const float* atd_wk_b = (const float*)d_in[9];
    const float* atd_wv_w = (const float*)d_in[10];
    const float* atd_wv_b = (const float*)d_in[11];
    const float* atd_sc   = (const float*)d_in[12];
    const float* aca_w    = (const float*)d_in[13];
    const float* aca_b    = (const float*)d_in[14];
    const float* win_rpb  = (const float*)d_in[15];
    const float* win_w    = (const float*)d_in[16];
    const float* win_b    = (const float*)d_in[17];
    const float* fctd_w   = (const float*)d_in[18];
    const float* fctd_b   = (const float*)d_in[19];
    const float* fc1_w    = (const float*)d_in[20];
    const float* fc1_b    = (const float*)d_in[21];
    const float* dw_w     = (const float*)d_in[22];
    const float* dw_b     = (const float*)d_in[23];
    const float* fc2_w    = (const float*)d_in[24];
    const float* fc2_b    = (const float*)d_in[25];
    const float* n2g      = (const float*)d_in[26];
    const float* n2b      = (const float*)d_in[27];
    const int*   rpi      = (const int*)d_in[28];
    float* out = (float*)d_out;

    float *xn, *qkv, *qatd, *kkn, *vv, *tdpr, *patd, *yaca, *ywin, *xsum, *x2n, *hc, *hc2;
    int *tkid, *sidx;
    cudaGetSymbolAddress((void**)&xn,   g_xn);
    cudaGetSymbolAddress((void**)&qkv,  g_qkv);
    cudaGetSymbolAddress((void**)&qatd, g_qatd);
    cudaGetSymbolAddress((void**)&kkn,  g_kkn);
    cudaGetSymbolAddress((void**)&vv,   g_vv);
    cudaGetSymbolAddress((void**)&tdpr, g_tdpr);
    cudaGetSymbolAddress((void**)&patd, g_patd);
    cudaGetSymbolAddress((void**)&yaca, g_yaca);
    cudaGetSymbolAddress((void**)&ywin, g_ywin);
    cudaGetSymbolAddress((void**)&xsum, g_xsum);
    cudaGetSymbolAddress((void**)&x2n,  g_x2n);
    cudaGetSymbolAddress((void**)&hc,   g_hc);
    cudaGetSymbolAddress((void**)&hc2,  g_hc2);
    cudaGetSymbolAddress((void**)&tkid, g_tkid);
    cudaGetSymbolAddress((void**)&sidx, g_sidx);

    // 1. dictionary projections
    dict_kernel<<<BATCH*MTOK, 256>>>(td, atd_wk_w, atd_wk_b, atd_wv_w, atd_wv_b,
                                     fctd_w, fctd_b, kkn, vv, tdpr);
    // 2. window bias expansion
    wbias_kernel<<<WINN*WINN/256, 256>>>(rpi, win_rpb);
    // 3. LN1 (+ fused q_atd projection)
    ln_kernel<<<ROWS/8, 256>>>(x, n1g, n1b, xn, atd_wq_w, atd_wq_b, qatd);
    // 4. qkv = xn @ wqkv + b
    gemm_tc<<<dim3(9, ROWS/128), 256>>>(xn, wqkv_w, DIMC, nullptr, nullptr, 0,
                                        nullptr, nullptr, 0, 0,
                                        wqkv_b, nullptr, nullptr,
                                        qkv, ROWS, QKVW, QKVW, 0);
    // 5. ATD probs + tk_id
    atd_kernel<<<ROWS/8, 256>>>(qatd, kkn, atd_sc, patd, tkid);
    // 6. window attention  (<- ncu captures this launch)
    cudaFuncSetAttribute(winattn_kernel, cudaFuncAttributeMaxDynamicSharedMemorySize, 65536);
    winattn_kernel<<<NWIN*HEADS, 256, 65536>>>(qkv, ywin);
    // 7. single-pass stable sort scatter
    sortscatter_kernel<<<BATCH*MTOK, 256>>>(tkid, sidx);
    // 8. grouped attention
    acmsa_kernel<<<BATCH*NG*HEADS, 128>>>(qkv, sidx, yaca);
    // 9. xsum = x + P@vv (batched) + yaca@aca_w + ywin@win_w + biases
    gemm_tc<<<dim3(3, ROWS/128), 256>>>(yaca, aca_w, DIMC, ywin, win_w, DIMC,
                                        patd, vv, (long)MTOK*DIMC, MTOK,
                                        aca_b, win_b, x,
                                        xsum, ROWS, DIMC, DIMC, 0);
    // 10. LN2
    ln_kernel<<<ROWS/8, 256>>>(xsum, n2g, n2b, x2n, nullptr, nullptr, nullptr);
    // 11. fc1 + GELU into hc[:, 0:360]
    gemm_tc<<<dim3(6, ROWS/128), 256>>>(x2n, fc1_w, DIMC, nullptr, nullptr, 0,
                                        nullptr, nullptr, 0, 0,
                                        fc1_b, nullptr, nullptr,
                                        hc, ROWS, MLP_HID, CFF, 1);
    // 12. gather td features into hc[:, 360:424]
    gathertd_kernel<<<ROWS*DTD/256, 256>>>(tdpr, tkid, hc);
    // 13. depthwise conv + gelu + residual (tiled)
    dwconv_kernel<<<dim3(16, CFF/DWCH, BATCH), 256>>>(hc, dw_w, dw_b, hc2);
    // 14. out = xsum + hc2 @ fc2_w + fc2_b
    gemm_tc<<<dim3(3, ROWS/128), 256>>>(hc2, fc2_w, CFF, nullptr, nullptr, 0,
                                        nullptr, nullptr, 0, 0,
                                        fc2_b, nullptr, xsum,
                                        out, ROWS, DIMC, DIMC, 0);
}